// round 6
// baseline (speedup 1.0000x reference)
#include <cuda_runtime.h>
#include <math.h>

#define NPOINTS 100000
#define BATCH   4096
#define KSEL    10
#define GRIDC   16
#define NCELLS  (GRIDC*GRIDC*GRIDC)
#define FULLMASK 0xffffffffu

// ---- device scratch (static: no allocations) ----
__device__ int    g_cnt[NCELLS];
__device__ int    g_off[NCELLS];
__device__ int    g_cur[NCELLS];
__device__ float  g_sx[NPOINTS], g_sy[NPOINTS], g_sz[NPOINTS], g_sw[NPOINTS];
__device__ int    g_sid[NPOINTS];
__device__ float4 g_cellmeta[NCELLS];
__device__ int    g_bbmin[3], g_bbmax[3];
__device__ float  g_lo[3], g_inv[3], g_cs[3], g_Rcell;

static __device__ __forceinline__ int f2ord(float f) {
    int i = __float_as_int(f);
    return (i >= 0) ? i : (i ^ 0x7fffffff);
}
static __device__ __forceinline__ float ord2f(int i) {
    return __int_as_float((i >= 0) ? i : (i ^ 0x7fffffff));
}
static __device__ __forceinline__ float sigmoidf_(float x) {
    return 1.0f / (1.0f + expf(-x));
}

#define INSERT(kv, ki)                                                   \
    do { float _v = (kv); int _i = (ki);                                 \
        _Pragma("unroll")                                                \
        for (int _j = 0; _j < KSEL; _j++) {                              \
            if (_v < hd[_j]) {                                           \
                float _tv = hd[_j]; hd[_j] = _v; _v = _tv;               \
                int _ti = hix[_j]; hix[_j] = _i; _i = _ti;               \
            }                                                            \
        }                                                                \
    } while (0)

// ---------------------------------------------------------------------------
// Preprocessing
// ---------------------------------------------------------------------------
__global__ void pre_init_kernel() {
    int i = blockIdx.x * blockDim.x + threadIdx.x;
    if (i < NCELLS) g_cnt[i] = 0;
    if (i == 0) {
        for (int a = 0; a < 3; a++) { g_bbmin[a] = 0x7fffffff; g_bbmax[a] = 0x80000000; }
    }
}

__global__ void pre_bbox_kernel(const float* __restrict__ xyz) {
    __shared__ int smn[3], smx[3];
    int tid = threadIdx.x;
    if (tid < 3) { smn[tid] = 0x7fffffff; smx[tid] = 0x80000000; }
    __syncthreads();
    int i = blockIdx.x * blockDim.x + tid;
    if (i < NPOINTS) {
        #pragma unroll
        for (int a = 0; a < 3; a++) {
            int o = f2ord(xyz[3*i+a]);
            atomicMin(&smn[a], o);
            atomicMax(&smx[a], o);
        }
    }
    __syncthreads();
    if (tid < 3) {
        atomicMin(&g_bbmin[tid], smn[tid]);
        atomicMax(&g_bbmax[tid], smx[tid]);
    }
}

__global__ void pre_grid_kernel() {
    if (threadIdx.x == 0 && blockIdx.x == 0) {
        float css[3];
        for (int a = 0; a < 3; a++) {
            float lo = ord2f(g_bbmin[a]) - 1e-5f;
            float hi = ord2f(g_bbmax[a]) + 1e-5f;
            float cs = fmaxf((hi - lo) / GRIDC, 1e-6f);
            g_lo[a] = lo; g_cs[a] = cs; g_inv[a] = 1.0f / cs;
            css[a] = cs;
        }
        g_Rcell = 0.5f * sqrtf(css[0]*css[0] + css[1]*css[1] + css[2]*css[2]);
    }
}

static __device__ __forceinline__ int cell_of(float x, float y, float z) {
    int ix = min(GRIDC-1, max(0, (int)((x - g_lo[0]) * g_inv[0])));
    int iy = min(GRIDC-1, max(0, (int)((y - g_lo[1]) * g_inv[1])));
    int iz = min(GRIDC-1, max(0, (int)((z - g_lo[2]) * g_inv[2])));
    return (iz * GRIDC + iy) * GRIDC + ix;
}

__global__ void pre_hist_kernel(const float* __restrict__ xyz) {
    int i = blockIdx.x * blockDim.x + threadIdx.x;
    if (i >= NPOINTS) return;
    atomicAdd(&g_cnt[cell_of(xyz[3*i], xyz[3*i+1], xyz[3*i+2])], 1);
}

__global__ __launch_bounds__(1024)
void pre_scan_kernel() {
    __shared__ int ssum[1024];
    int t = threadIdx.x;
    int v0 = g_cnt[t*4+0], v1 = g_cnt[t*4+1], v2 = g_cnt[t*4+2], v3 = g_cnt[t*4+3];
    int s = v0 + v1 + v2 + v3;
    ssum[t] = s;
    __syncthreads();
    for (int off = 1; off < 1024; off <<= 1) {
        int x = (t >= off) ? ssum[t - off] : 0;
        __syncthreads();
        ssum[t] += x;
        __syncthreads();
    }
    int excl = ssum[t] - s;
    g_off[t*4+0] = excl;          g_cur[t*4+0] = excl;
    g_off[t*4+1] = excl + v0;     g_cur[t*4+1] = excl + v0;
    g_off[t*4+2] = excl + v0+v1;  g_cur[t*4+2] = excl + v0+v1;
    g_off[t*4+3] = excl + v0+v1+v2; g_cur[t*4+3] = excl + v0+v1+v2;
    // cell centers
    for (int c = t; c < NCELLS; c += 1024) {
        int ix = c & (GRIDC-1), iy = (c >> 4) & (GRIDC-1), iz = c >> 8;
        float gx = g_lo[0] + (ix + 0.5f) * g_cs[0];
        float gy = g_lo[1] + (iy + 0.5f) * g_cs[1];
        float gz = g_lo[2] + (iz + 0.5f) * g_cs[2];
        g_cellmeta[c] = make_float4(gx, gy, gz, gx*gx + gy*gy + gz*gz);
    }
}

__global__ void pre_scatter_kernel(const float* __restrict__ xyz) {
    int i = blockIdx.x * blockDim.x + threadIdx.x;
    if (i >= NPOINTS) return;
    float x = xyz[3*i], y = xyz[3*i+1], z = xyz[3*i+2];
    int c = cell_of(x, y, z);
    int pos = atomicAdd(&g_cur[c], 1);
    g_sx[pos] = x; g_sy[pos] = y; g_sz[pos] = z;
    g_sw[pos] = fmaf(x, x, fmaf(y, y, z*z));
    g_sid[pos] = i;
}

// ---------------------------------------------------------------------------
// Main: one warp per ray; cell screening + exact candidate scan
// ---------------------------------------------------------------------------
__global__ __launch_bounds__(1024, 1)
void gsplat_spatial_kernel(const float* __restrict__ rays_o,
                           const float* __restrict__ rays_d,
                           const float* __restrict__ xyz,
                           const float* __restrict__ fdc,
                           const float* __restrict__ opacity,
                           float* __restrict__ out)
{
    extern __shared__ float4 smcells[];   // NCELLS entries (64 KB)
    const int tid  = threadIdx.x;
    const int lane = tid & 31;
    const int wid  = tid >> 5;
    const int ray  = blockIdx.x * 32 + wid;
    const float POSINF = __int_as_float(0x7f800000);

    for (int i = tid; i < NCELLS; i += 1024) smcells[i] = g_cellmeta[i];
    __syncthreads();

    float ox = rays_o[3*ray+0], oy = rays_o[3*ray+1], oz = rays_o[3*ray+2];
    float dx = rays_d[3*ray+0], dy = rays_d[3*ray+1], dz = rays_d[3*ray+2];
    float cx = fmaf(dx, 3.0f, ox);
    float cy = fmaf(dy, 3.0f, oy);
    float cz = fmaf(dz, 3.0f, oz);
    float ax = -2.0f*cx, ay = -2.0f*cy, az = -2.0f*cz;
    float cn2 = cx*cx + cy*cy + cz*cz;
    const float R = g_Rcell;

    float hd[KSEL]; int hix[KSEL];
    #pragma unroll
    for (int j = 0; j < KSEL; j++) { hd[j] = POSINF; hix[j] = 0; }
    float thr = POSINF;

    // ---- seed: 32 strided samples (exact inserts; fills heap, tightens thr) ----
    {
        int p = lane * (NPOINTS / 32);       // 3125 stride
        float px = xyz[3*p], py = xyz[3*p+1], pz = xyz[3*p+2];
        float pw = fmaf(px, px, fmaf(py, py, pz*pz));
        float key = fmaf(px, ax, fmaf(py, ay, fmaf(pz, az, pw)));
        for (int src = 0; src < 32; src++) {
            float kv = __shfl_sync(FULLMASK, key, src);
            if (kv < thr) {
                INSERT(kv, src * (NPOINTS / 32));
                thr = hd[KSEL-1];
            }
        }
    }
    float T = sqrtf(fmaxf(thr + cn2, 0.0f));
    float thr2 = thr + fmaf(2.0f*T, R, R*R);

    // ---- cell screening + candidate processing ----
    for (int cb = 0; cb < NCELLS; cb += 32) {
        float4 m = smcells[cb + lane];
        float gkey = fmaf(m.x, ax, fmaf(m.y, ay, fmaf(m.z, az, m.w)));
        unsigned pm = __ballot_sync(FULLMASK, gkey < thr2);
        while (pm) {
            int src = __ffs(pm) - 1;
            pm &= pm - 1;
            float ck = __shfl_sync(FULLMASK, gkey, src);
            if (ck < thr2) {                      // re-check vs tightened thr2
                int cell = cb + src;
                int s = __ldg(&g_off[cell]);      // uniform → broadcast
                int n = __ldg(&g_cnt[cell]);
                for (int g0 = 0; g0 < n; g0 += 32) {
                    float key = POSINF;
                    bool act = (g0 + lane) < n;
                    if (act) {
                        int i = s + g0 + lane;
                        float px = __ldg(&g_sx[i]);
                        float py = __ldg(&g_sy[i]);
                        float pz = __ldg(&g_sz[i]);
                        float pw = __ldg(&g_sw[i]);
                        key = fmaf(px, ax, fmaf(py, ay, fmaf(pz, az, pw)));
                    }
                    unsigned im = __ballot_sync(FULLMASK, key < thr);
                    while (im) {
                        int isrc = __ffs(im) - 1;
                        im &= im - 1;
                        float kv = __shfl_sync(FULLMASK, key, isrc);
                        if (kv < thr) {
                            int pid = __ldg(&g_sid[s + g0 + isrc]);
                            INSERT(kv, pid);
                            thr = hd[KSEL-1];
                        }
                    }
                }
                T = sqrtf(fmaxf(thr + cn2, 0.0f));
                thr2 = thr + fmaf(2.0f*T, R, R*R);
            }
        }
    }

    // ---- epilogue (lane 0; all lanes hold identical heaps) ----
    if (lane == 0) {
        float ws = 0.f, s0 = 0.f, s1 = 0.f, s2 = 0.f;
        #pragma unroll
        for (int k = 0; k < KSEL; k++) {
            float dist = sqrtf(fmaxf(hd[k] + cn2, 0.0f));
            int id = hix[k];
            float op = opacity[id];
            float w = expf(-0.1f * dist) * sigmoidf_(op);
            ws += w;
            s0 = fmaf(w, sigmoidf_(fdc[3*id+0]), s0);
            s1 = fmaf(w, sigmoidf_(fdc[3*id+1]), s1);
            s2 = fmaf(w, sigmoidf_(fdc[3*id+2]), s2);
        }
        float inv = 1.0f / (ws + 1e-8f);
        out[3*ray+0] = s0 * inv;
        out[3*ray+1] = s1 * inv;
        out[3*ray+2] = s2 * inv;
    }
}

extern "C" void kernel_launch(void* const* d_in, const int* in_sizes, int n_in,
                              void* d_out, int out_size)
{
    const float* rays_o  = (const float*)d_in[0];
    const float* rays_d  = (const float*)d_in[1];
    const float* xyz     = (const float*)d_in[2];
    const float* fdc     = (const float*)d_in[3];
    const float* opacity = (const float*)d_in[4];
    float* out = (float*)d_out;

    const int smem = NCELLS * sizeof(float4);   // 64 KB
    static bool attr_set = false;
    if (!attr_set) {
        cudaFuncSetAttribute(gsplat_spatial_kernel,
                             cudaFuncAttributeMaxDynamicSharedMemorySize, smem);
        attr_set = true;
    }

    const int PB = (NPOINTS + 1023) / 1024;   // 98 blocks for point-parallel passes
    pre_init_kernel<<<(NCELLS + 1023) / 1024, 1024>>>();
    pre_bbox_kernel<<<PB, 1024>>>(xyz);
    pre_grid_kernel<<<1, 32>>>();
    pre_hist_kernel<<<PB, 1024>>>(xyz);
    pre_scan_kernel<<<1, 1024>>>();
    pre_scatter_kernel<<<PB, 1024>>>(xyz);
    gsplat_spatial_kernel<<<BATCH / 32, 1024, smem>>>(
        rays_o, rays_d, xyz, fdc, opacity, out);
}

// round 7
// speedup vs baseline: 1.2802x; 1.2802x over previous
#include <cuda_runtime.h>
#include <math.h>

#define NPOINTS 100000
#define BATCH   4096
#define KSEL    10
#define GRIDC   16
#define NCELLS  (GRIDC*GRIDC*GRIDC)
#define SEEDSTR 390            // 256 seeds, stride 390 -> max idx 99450
#define FULLMASK 0xffffffffu
#define WPB     8
#define TPB     256

// ---- device scratch (static: no allocations) ----
__device__ int    g_cnt[NCELLS];
__device__ int    g_off[NCELLS];
__device__ int    g_cur[NCELLS];
__device__ float  g_sx[NPOINTS], g_sy[NPOINTS], g_sz[NPOINTS], g_sw[NPOINTS];
__device__ int    g_sid[NPOINTS];
__device__ float4 g_cellmeta[NCELLS];
__device__ int    g_bbmin[3] = {0x7fffffff, 0x7fffffff, 0x7fffffff};
__device__ int    g_bbmax[3] = {0x80000000, 0x80000000, 0x80000000};
__device__ float  g_lo[3], g_invc[3], g_cs[3], g_Rcell;

static __device__ __forceinline__ int f2ord(float f) {
    int i = __float_as_int(f);
    return (i >= 0) ? i : (i ^ 0x7fffffff);
}
static __device__ __forceinline__ float ord2f(int i) {
    return __int_as_float((i >= 0) ? i : (i ^ 0x7fffffff));
}
static __device__ __forceinline__ float sigmoidf_(float x) {
    return 1.0f / (1.0f + expf(-x));
}

#define INSERT(kv, ki)                                                   \
    do { float _v = (kv); int _i = (ki);                                 \
        _Pragma("unroll")                                                \
        for (int _j = 0; _j < KSEL; _j++) {                              \
            if (_v < hd[_j]) {                                           \
                float _tv = hd[_j]; hd[_j] = _v; _v = _tv;               \
                int _ti = hix[_j]; hix[_j] = _i; _i = _ti;               \
            }                                                            \
        }                                                                \
    } while (0)

// ---------------------------------------------------------------------------
// Preprocessing (5 launches)
// ---------------------------------------------------------------------------
__global__ void pre_bbox_kernel(const float* __restrict__ xyz) {
    int i = blockIdx.x * blockDim.x + threadIdx.x;
    if (i < NCELLS) g_cnt[i] = 0;          // zero histogram for this run
    int mn0, mn1, mn2, mx0, mx1, mx2;
    if (i < NPOINTS) {
        mn0 = mx0 = f2ord(xyz[3*i+0]);
        mn1 = mx1 = f2ord(xyz[3*i+1]);
        mn2 = mx2 = f2ord(xyz[3*i+2]);
    } else {
        mn0 = mn1 = mn2 = 0x7fffffff;
        mx0 = mx1 = mx2 = 0x80000000;
    }
    mn0 = __reduce_min_sync(FULLMASK, mn0);
    mn1 = __reduce_min_sync(FULLMASK, mn1);
    mn2 = __reduce_min_sync(FULLMASK, mn2);
    mx0 = __reduce_max_sync(FULLMASK, mx0);
    mx1 = __reduce_max_sync(FULLMASK, mx1);
    mx2 = __reduce_max_sync(FULLMASK, mx2);
    if ((threadIdx.x & 31) == 0) {
        atomicMin(&g_bbmin[0], mn0); atomicMax(&g_bbmax[0], mx0);
        atomicMin(&g_bbmin[1], mn1); atomicMax(&g_bbmax[1], mx1);
        atomicMin(&g_bbmin[2], mn2); atomicMax(&g_bbmax[2], mx2);
    }
}

__global__ void pre_grid_kernel() {
    if (threadIdx.x == 0) {
        float css[3];
        for (int a = 0; a < 3; a++) {
            float lo = ord2f(g_bbmin[a]) - 1e-5f;
            float hi = ord2f(g_bbmax[a]) + 1e-5f;
            float cs = fmaxf((hi - lo) / GRIDC, 1e-6f);
            g_lo[a] = lo; g_cs[a] = cs; g_invc[a] = 1.0f / cs;
            css[a] = cs;
        }
        g_Rcell = 0.5f * sqrtf(css[0]*css[0] + css[1]*css[1] + css[2]*css[2]);
    }
}

static __device__ __forceinline__ int cell_of(float x, float y, float z) {
    int ix = min(GRIDC-1, max(0, (int)((x - g_lo[0]) * g_invc[0])));
    int iy = min(GRIDC-1, max(0, (int)((y - g_lo[1]) * g_invc[1])));
    int iz = min(GRIDC-1, max(0, (int)((z - g_lo[2]) * g_invc[2])));
    return (iz * GRIDC + iy) * GRIDC + ix;
}

__global__ void pre_hist_kernel(const float* __restrict__ xyz) {
    int i = blockIdx.x * blockDim.x + threadIdx.x;
    if (i >= NPOINTS) return;
    atomicAdd(&g_cnt[cell_of(xyz[3*i], xyz[3*i+1], xyz[3*i+2])], 1);
}

__global__ __launch_bounds__(1024)
void pre_scan_kernel() {
    __shared__ int ssum[1024];
    int t = threadIdx.x;
    int v0 = g_cnt[t*4+0], v1 = g_cnt[t*4+1], v2 = g_cnt[t*4+2], v3 = g_cnt[t*4+3];
    int s = v0 + v1 + v2 + v3;
    ssum[t] = s;
    __syncthreads();
    for (int off = 1; off < 1024; off <<= 1) {
        int x = (t >= off) ? ssum[t - off] : 0;
        __syncthreads();
        ssum[t] += x;
        __syncthreads();
    }
    int excl = ssum[t] - s;
    g_off[t*4+0] = excl;            g_cur[t*4+0] = excl;
    g_off[t*4+1] = excl + v0;       g_cur[t*4+1] = excl + v0;
    g_off[t*4+2] = excl + v0+v1;    g_cur[t*4+2] = excl + v0+v1;
    g_off[t*4+3] = excl + v0+v1+v2; g_cur[t*4+3] = excl + v0+v1+v2;
    for (int c = t; c < NCELLS; c += 1024) {
        int ix = c & (GRIDC-1), iy = (c >> 4) & (GRIDC-1), iz = c >> 8;
        float gx = g_lo[0] + (ix + 0.5f) * g_cs[0];
        float gy = g_lo[1] + (iy + 0.5f) * g_cs[1];
        float gz = g_lo[2] + (iz + 0.5f) * g_cs[2];
        g_cellmeta[c] = make_float4(gx, gy, gz, gx*gx + gy*gy + gz*gz);
    }
}

__global__ void pre_scatter_kernel(const float* __restrict__ xyz) {
    int i = blockIdx.x * blockDim.x + threadIdx.x;
    if (i >= NPOINTS) return;
    float x = xyz[3*i], y = xyz[3*i+1], z = xyz[3*i+2];
    int c = cell_of(x, y, z);
    int pos = atomicAdd(&g_cur[c], 1);
    g_sx[pos] = x; g_sy[pos] = y; g_sz[pos] = z;
    g_sw[pos] = fmaf(x, x, fmaf(y, y, z*z));
    g_sid[pos] = i;
}

// ---------------------------------------------------------------------------
// Main: one warp per ray; seed + cell screening + exact candidate scan
// ---------------------------------------------------------------------------
__global__ __launch_bounds__(TPB)
void gsplat_spatial_kernel(const float* __restrict__ rays_o,
                           const float* __restrict__ rays_d,
                           const float* __restrict__ xyz,
                           const float* __restrict__ fdc,
                           const float* __restrict__ opacity,
                           float* __restrict__ out)
{
    extern __shared__ float4 smcells[];   // NCELLS entries (64 KB)
    const int tid  = threadIdx.x;
    const int lane = tid & 31;
    const int wid  = tid >> 5;
    const int ray  = blockIdx.x * WPB + wid;
    const float POSINF = __int_as_float(0x7f800000);

    for (int i = tid; i < NCELLS; i += TPB) smcells[i] = g_cellmeta[i];
    __syncthreads();

    float ox = rays_o[3*ray+0], oy = rays_o[3*ray+1], oz = rays_o[3*ray+2];
    float dx = rays_d[3*ray+0], dy = rays_d[3*ray+1], dz = rays_d[3*ray+2];
    float cx = fmaf(dx, 3.0f, ox);
    float cy = fmaf(dy, 3.0f, oy);
    float cz = fmaf(dz, 3.0f, oz);
    float ax = -2.0f*cx, ay = -2.0f*cy, az = -2.0f*cz;
    float cn2 = cx*cx + cy*cy + cz*cz;
    const float R = g_Rcell;

    float hd[KSEL]; int hix[KSEL];
    #pragma unroll
    for (int j = 0; j < KSEL; j++) { hd[j] = POSINF; hix[j] = -1; }
    float thr = POSINF;

    // ---- seed: 256 strided samples (prefetched keys, then exact inserts) ----
    float skey[8];
    #pragma unroll
    for (int it = 0; it < 8; it++) {
        int p = (it * 32 + lane) * SEEDSTR;
        float px = __ldg(&xyz[3*p]), py = __ldg(&xyz[3*p+1]), pz = __ldg(&xyz[3*p+2]);
        float pw = fmaf(px, px, fmaf(py, py, pz*pz));
        skey[it] = fmaf(px, ax, fmaf(py, ay, fmaf(pz, az, pw)));
    }
    #pragma unroll
    for (int it = 0; it < 8; it++) {
        unsigned m = __ballot_sync(FULLMASK, skey[it] < thr);
        while (m) {
            int src = __ffs(m) - 1;
            m &= m - 1;
            float kv = __shfl_sync(FULLMASK, skey[it], src);
            if (kv < thr) {
                INSERT(kv, (it * 32 + src) * SEEDSTR);
                thr = hd[KSEL-1];
            }
        }
    }
    float T = sqrtf(fmaxf(thr + cn2, 0.0f));
    float thr2 = thr + fmaf(2.0f * T, R, R * R);

    // ---- cell screening + candidate processing ----
    for (int cb = 0; cb < NCELLS; cb += 32) {
        float4 m4 = smcells[cb + lane];
        float gkey = fmaf(m4.x, ax, fmaf(m4.y, ay, fmaf(m4.z, az, m4.w)));
        unsigned pm = __ballot_sync(FULLMASK, gkey < thr2);
        while (pm) {
            int src = __ffs(pm) - 1;
            pm &= pm - 1;
            float ck = __shfl_sync(FULLMASK, gkey, src);
            if (ck < thr2) {                   // re-check vs tightened thr2
                int cell = cb + src;
                int s = g_off[cell];           // warp-uniform -> broadcast
                int n = g_cnt[cell];
                for (int g0 = 0; g0 < n; g0 += 32) {
                    float key = POSINF;
                    if (g0 + lane < n) {
                        int i = s + g0 + lane;
                        float px = __ldg(&g_sx[i]);
                        float py = __ldg(&g_sy[i]);
                        float pz = __ldg(&g_sz[i]);
                        float pw = __ldg(&g_sw[i]);
                        key = fmaf(px, ax, fmaf(py, ay, fmaf(pz, az, pw)));
                    }
                    unsigned im = __ballot_sync(FULLMASK, key < thr);
                    while (im) {
                        int is = __ffs(im) - 1;
                        im &= im - 1;
                        float kv = __shfl_sync(FULLMASK, key, is);
                        if (kv < thr) {
                            int pid = __ldg(&g_sid[s + g0 + is]);
                            bool dup = false;     // seeds may be re-scanned
                            #pragma unroll
                            for (int j = 0; j < KSEL; j++) dup |= (hix[j] == pid);
                            if (!dup) {
                                INSERT(kv, pid);
                                thr = hd[KSEL-1];
                            }
                        }
                    }
                }
                T = sqrtf(fmaxf(thr + cn2, 0.0f));
                thr2 = thr + fmaf(2.0f * T, R, R * R);
            }
        }
    }

    // ---- epilogue (lane 0; all lanes hold identical heaps) ----
    if (lane == 0) {
        float ws = 0.f, s0 = 0.f, s1 = 0.f, s2 = 0.f;
        #pragma unroll
        for (int k = 0; k < KSEL; k++) {
            float dist = sqrtf(fmaxf(hd[k] + cn2, 0.0f));
            int id = hix[k];
            float op = opacity[id];
            float w = expf(-0.1f * dist) * sigmoidf_(op);
            ws += w;
            s0 = fmaf(w, sigmoidf_(fdc[3*id+0]), s0);
            s1 = fmaf(w, sigmoidf_(fdc[3*id+1]), s1);
            s2 = fmaf(w, sigmoidf_(fdc[3*id+2]), s2);
        }
        float inv = 1.0f / (ws + 1e-8f);
        out[3*ray+0] = s0 * inv;
        out[3*ray+1] = s1 * inv;
        out[3*ray+2] = s2 * inv;
    }
}

extern "C" void kernel_launch(void* const* d_in, const int* in_sizes, int n_in,
                              void* d_out, int out_size)
{
    const float* rays_o  = (const float*)d_in[0];
    const float* rays_d  = (const float*)d_in[1];
    const float* xyz     = (const float*)d_in[2];
    const float* fdc     = (const float*)d_in[3];
    const float* opacity = (const float*)d_in[4];
    float* out = (float*)d_out;

    const int smem = NCELLS * sizeof(float4);   // 64 KB
    static bool attr_set = false;
    if (!attr_set) {
        cudaFuncSetAttribute(gsplat_spatial_kernel,
                             cudaFuncAttributeMaxDynamicSharedMemorySize, smem);
        attr_set = true;
    }

    const int PB = (NPOINTS + 1023) / 1024;
    pre_bbox_kernel<<<PB, 1024>>>(xyz);
    pre_grid_kernel<<<1, 32>>>();
    pre_hist_kernel<<<PB, 1024>>>(xyz);
    pre_scan_kernel<<<1, 1024>>>();
    pre_scatter_kernel<<<PB, 1024>>>(xyz);
    gsplat_spatial_kernel<<<BATCH / WPB, TPB, smem>>>(
        rays_o, rays_d, xyz, fdc, opacity, out);
}

// round 8
// speedup vs baseline: 1.7446x; 1.3627x over previous
#include <cuda_runtime.h>
#include <math.h>

#define NPOINTS 100000
#define BATCH   4096
#define KSEL    10
#define GRIDC   16
#define NCELLS  (GRIDC*GRIDC*GRIDC)
#define SEEDSTR 390            // 256 seeds, stride 390 -> max idx 99450
#define FULLMASK 0xffffffffu
#define WPB     16
#define TPB     512

// ---- device scratch (static: no allocations) ----
__device__ int    g_cnt[NCELLS];
__device__ int    g_off[NCELLS];
__device__ int    g_cur[NCELLS];
__device__ float4 g_pts[NPOINTS];        // (x, y, z, |p|^2), cell-sorted
__device__ int    g_sid[NPOINTS];
__device__ float4 g_cellmeta[NCELLS];    // (cx, cy, cz, |c|^2)
__device__ int    g_bbmin[3] = {0x7fffffff, 0x7fffffff, 0x7fffffff};
__device__ int    g_bbmax[3] = {0x80000000, 0x80000000, 0x80000000};
__device__ float  g_lo[3], g_invc[3], g_cs[3], g_Rcell;

static __device__ __forceinline__ int f2ord(float f) {
    int i = __float_as_int(f);
    return (i >= 0) ? i : (i ^ 0x7fffffff);
}
static __device__ __forceinline__ float ord2f(int i) {
    return __int_as_float((i >= 0) ? i : (i ^ 0x7fffffff));
}
static __device__ __forceinline__ float sigmoidf_(float x) {
    return 1.0f / (1.0f + expf(-x));
}

#define INSERT(kv, ki)                                                   \
    do { float _v = (kv); int _i = (ki);                                 \
        _Pragma("unroll")                                                \
        for (int _j = 0; _j < KSEL; _j++) {                              \
            if (_v < hd[_j]) {                                           \
                float _tv = hd[_j]; hd[_j] = _v; _v = _tv;               \
                int _ti = hix[_j]; hix[_j] = _i; _i = _ti;               \
            }                                                            \
        }                                                                \
    } while (0)

// ---------------------------------------------------------------------------
// Preprocessing
// ---------------------------------------------------------------------------
__global__ void pre_bbox_kernel(const float* __restrict__ xyz) {
    int i = blockIdx.x * blockDim.x + threadIdx.x;
    if (i < NCELLS) g_cnt[i] = 0;
    int mn0, mn1, mn2, mx0, mx1, mx2;
    if (i < NPOINTS) {
        mn0 = mx0 = f2ord(xyz[3*i+0]);
        mn1 = mx1 = f2ord(xyz[3*i+1]);
        mn2 = mx2 = f2ord(xyz[3*i+2]);
    } else {
        mn0 = mn1 = mn2 = 0x7fffffff;
        mx0 = mx1 = mx2 = 0x80000000;
    }
    mn0 = __reduce_min_sync(FULLMASK, mn0);
    mn1 = __reduce_min_sync(FULLMASK, mn1);
    mn2 = __reduce_min_sync(FULLMASK, mn2);
    mx0 = __reduce_max_sync(FULLMASK, mx0);
    mx1 = __reduce_max_sync(FULLMASK, mx1);
    mx2 = __reduce_max_sync(FULLMASK, mx2);
    if ((threadIdx.x & 31) == 0) {
        atomicMin(&g_bbmin[0], mn0); atomicMax(&g_bbmax[0], mx0);
        atomicMin(&g_bbmin[1], mn1); atomicMax(&g_bbmax[1], mx1);
        atomicMin(&g_bbmin[2], mn2); atomicMax(&g_bbmax[2], mx2);
    }
}

__global__ void pre_grid_kernel() {
    if (threadIdx.x == 0) {
        float css[3];
        for (int a = 0; a < 3; a++) {
            float lo = ord2f(g_bbmin[a]) - 1e-5f;
            float hi = ord2f(g_bbmax[a]) + 1e-5f;
            float cs = fmaxf((hi - lo) / GRIDC, 1e-6f);
            g_lo[a] = lo; g_cs[a] = cs; g_invc[a] = 1.0f / cs;
            css[a] = cs;
        }
        g_Rcell = 0.5f * sqrtf(css[0]*css[0] + css[1]*css[1] + css[2]*css[2]);
    }
}

static __device__ __forceinline__ int cell_of(float x, float y, float z) {
    int ix = min(GRIDC-1, max(0, (int)((x - g_lo[0]) * g_invc[0])));
    int iy = min(GRIDC-1, max(0, (int)((y - g_lo[1]) * g_invc[1])));
    int iz = min(GRIDC-1, max(0, (int)((z - g_lo[2]) * g_invc[2])));
    return (iz * GRIDC + iy) * GRIDC + ix;
}

__global__ void pre_hist_kernel(const float* __restrict__ xyz) {
    int i = blockIdx.x * blockDim.x + threadIdx.x;
    if (i >= NPOINTS) return;
    atomicAdd(&g_cnt[cell_of(xyz[3*i], xyz[3*i+1], xyz[3*i+2])], 1);
}

__global__ __launch_bounds__(1024)
void pre_scan_kernel() {
    __shared__ int ssum[1024];
    int t = threadIdx.x;
    int v0 = g_cnt[t*4+0], v1 = g_cnt[t*4+1], v2 = g_cnt[t*4+2], v3 = g_cnt[t*4+3];
    int s = v0 + v1 + v2 + v3;
    ssum[t] = s;
    __syncthreads();
    for (int off = 1; off < 1024; off <<= 1) {
        int x = (t >= off) ? ssum[t - off] : 0;
        __syncthreads();
        ssum[t] += x;
        __syncthreads();
    }
    int excl = ssum[t] - s;
    g_off[t*4+0] = excl;            g_cur[t*4+0] = excl;
    g_off[t*4+1] = excl + v0;       g_cur[t*4+1] = excl + v0;
    g_off[t*4+2] = excl + v0+v1;    g_cur[t*4+2] = excl + v0+v1;
    g_off[t*4+3] = excl + v0+v1+v2; g_cur[t*4+3] = excl + v0+v1+v2;
    for (int c = t; c < NCELLS; c += 1024) {
        int ix = c & (GRIDC-1), iy = (c >> 4) & (GRIDC-1), iz = c >> 8;
        float gx = g_lo[0] + (ix + 0.5f) * g_cs[0];
        float gy = g_lo[1] + (iy + 0.5f) * g_cs[1];
        float gz = g_lo[2] + (iz + 0.5f) * g_cs[2];
        g_cellmeta[c] = make_float4(gx, gy, gz, gx*gx + gy*gy + gz*gz);
    }
}

__global__ void pre_scatter_kernel(const float* __restrict__ xyz) {
    int i = blockIdx.x * blockDim.x + threadIdx.x;
    if (i >= NPOINTS) return;
    float x = xyz[3*i], y = xyz[3*i+1], z = xyz[3*i+2];
    int c = cell_of(x, y, z);
    int pos = atomicAdd(&g_cur[c], 1);
    g_pts[pos] = make_float4(x, y, z, fmaf(x, x, fmaf(y, y, z*z)));
    g_sid[pos] = i;
}

// ---------------------------------------------------------------------------
// Main: one warp per ray; seed -> best cell first -> conservative sweep
// ---------------------------------------------------------------------------
__global__ __launch_bounds__(TPB)
void gsplat_spatial_kernel(const float* __restrict__ rays_o,
                           const float* __restrict__ rays_d,
                           const float* __restrict__ xyz,
                           const float* __restrict__ fdc,
                           const float* __restrict__ opacity,
                           float* __restrict__ out)
{
    extern __shared__ char smraw[];
    float4* smc = (float4*)smraw;                        // cell meta   (64 KB)
    int2*   soc = (int2*)(smraw + NCELLS * 16);          // (off, cnt)  (32 KB)

    const int tid  = threadIdx.x;
    const int lane = tid & 31;
    const int wid  = tid >> 5;
    const int ray  = blockIdx.x * WPB + wid;
    const float POSINF = __int_as_float(0x7f800000);

    for (int i = tid; i < NCELLS; i += TPB) {
        smc[i] = g_cellmeta[i];
        soc[i] = make_int2(g_off[i], g_cnt[i]);
    }
    __syncthreads();

    float ox = rays_o[3*ray+0], oy = rays_o[3*ray+1], oz = rays_o[3*ray+2];
    float dx = rays_d[3*ray+0], dy = rays_d[3*ray+1], dz = rays_d[3*ray+2];
    float cx = fmaf(dx, 3.0f, ox);
    float cy = fmaf(dy, 3.0f, oy);
    float cz = fmaf(dz, 3.0f, oz);
    float ax = -2.0f*cx, ay = -2.0f*cy, az = -2.0f*cz;
    float cn2 = cx*cx + cy*cy + cz*cz;
    const float R = g_Rcell;

    float hd[KSEL]; int hix[KSEL];
    #pragma unroll
    for (int j = 0; j < KSEL; j++) { hd[j] = POSINF; hix[j] = -1; }
    float thr = POSINF;

    // ---- seed: 256 strided samples (fills heap with real entries) ----
    float skey[8];
    #pragma unroll
    for (int it = 0; it < 8; it++) {
        int p = (it * 32 + lane) * SEEDSTR;
        float px = __ldg(&xyz[3*p]), py = __ldg(&xyz[3*p+1]), pz = __ldg(&xyz[3*p+2]);
        float pw = fmaf(px, px, fmaf(py, py, pz*pz));
        skey[it] = fmaf(px, ax, fmaf(py, ay, fmaf(pz, az, pw)));
    }
    #pragma unroll
    for (int it = 0; it < 8; it++) {
        unsigned m = __ballot_sync(FULLMASK, skey[it] < thr);
        while (m) {
            int src = __ffs(m) - 1;
            m &= m - 1;
            float kv = __shfl_sync(FULLMASK, skey[it], src);
            if (kv < thr) {
                INSERT(kv, (it * 32 + src) * SEEDSTR);
                thr = hd[KSEL-1];
            }
        }
    }

    // ---- phase A: find the single nearest cell (warp argmin over 4096) ----
    float bmin = POSINF; int bcell = 0;
    for (int cb = 0; cb < NCELLS; cb += 32) {
        float4 m4 = smc[cb + lane];
        float gk = fmaf(m4.x, ax, fmaf(m4.y, ay, fmaf(m4.z, az, m4.w)));
        if (gk < bmin) { bmin = gk; bcell = cb + lane; }
    }
    #pragma unroll
    for (int off = 16; off; off >>= 1) {
        float ov = __shfl_xor_sync(FULLMASK, bmin, off);
        int   oc = __shfl_xor_sync(FULLMASK, bcell, off);
        if (ov < bmin || (ov == bmin && oc < bcell)) { bmin = ov; bcell = oc; }
    }

    // ---- scan best cell first (tightens thr to ~true d10) ----
    {
        int2 oc = soc[bcell];
        for (int g0 = 0; g0 < oc.y; g0 += 32) {
            float key = POSINF;
            if (g0 + lane < oc.y) {
                float4 p = __ldg(&g_pts[oc.x + g0 + lane]);
                key = fmaf(p.x, ax, fmaf(p.y, ay, fmaf(p.z, az, p.w)));
            }
            unsigned im = __ballot_sync(FULLMASK, key < thr);
            while (im) {
                int is = __ffs(im) - 1;
                im &= im - 1;
                float kv = __shfl_sync(FULLMASK, key, is);
                if (kv < thr) {
                    int pid = __ldg(&g_sid[oc.x + g0 + is]);
                    bool dup = false;
                    #pragma unroll
                    for (int j = 0; j < KSEL; j++) dup |= (hix[j] == pid);
                    if (!dup) { INSERT(kv, pid); thr = hd[KSEL-1]; }
                }
            }
        }
    }
    float T = sqrtf(fmaxf(thr + cn2, 0.0f));
    float thr2 = thr + fmaf(2.0f * T, R, R * R);

    // ---- conservative sweep over remaining cells ----
    for (int cb = 0; cb < NCELLS; cb += 32) {
        float4 m4 = smc[cb + lane];
        float gk = fmaf(m4.x, ax, fmaf(m4.y, ay, fmaf(m4.z, az, m4.w)));
        unsigned pm = __ballot_sync(FULLMASK, (gk < thr2) && (cb + lane != bcell));
        while (pm) {
            int src = __ffs(pm) - 1;
            pm &= pm - 1;
            float ck = __shfl_sync(FULLMASK, gk, src);
            if (ck < thr2) {                   // re-check vs tightened thr2
                int2 oc = soc[cb + src];       // warp-uniform -> LDS broadcast
                for (int g0 = 0; g0 < oc.y; g0 += 32) {
                    float key = POSINF;
                    if (g0 + lane < oc.y) {
                        float4 p = __ldg(&g_pts[oc.x + g0 + lane]);
                        key = fmaf(p.x, ax, fmaf(p.y, ay, fmaf(p.z, az, p.w)));
                    }
                    unsigned im = __ballot_sync(FULLMASK, key < thr);
                    while (im) {
                        int is = __ffs(im) - 1;
                        im &= im - 1;
                        float kv = __shfl_sync(FULLMASK, key, is);
                        if (kv < thr) {
                            int pid = __ldg(&g_sid[oc.x + g0 + is]);
                            bool dup = false;
                            #pragma unroll
                            for (int j = 0; j < KSEL; j++) dup |= (hix[j] == pid);
                            if (!dup) { INSERT(kv, pid); thr = hd[KSEL-1]; }
                        }
                    }
                }
                T = sqrtf(fmaxf(thr + cn2, 0.0f));
                thr2 = thr + fmaf(2.0f * T, R, R * R);
            }
        }
    }

    // ---- epilogue (lane 0; all lanes hold identical heaps) ----
    if (lane == 0) {
        float ws = 0.f, s0 = 0.f, s1 = 0.f, s2 = 0.f;
        #pragma unroll
        for (int k = 0; k < KSEL; k++) {
            float dist = sqrtf(fmaxf(hd[k] + cn2, 0.0f));
            int id = hix[k];
            float op = opacity[id];
            float w = expf(-0.1f * dist) * sigmoidf_(op);
            ws += w;
            s0 = fmaf(w, sigmoidf_(fdc[3*id+0]), s0);
            s1 = fmaf(w, sigmoidf_(fdc[3*id+1]), s1);
            s2 = fmaf(w, sigmoidf_(fdc[3*id+2]), s2);
        }
        float inv = 1.0f / (ws + 1e-8f);
        out[3*ray+0] = s0 * inv;
        out[3*ray+1] = s1 * inv;
        out[3*ray+2] = s2 * inv;
    }
}

extern "C" void kernel_launch(void* const* d_in, const int* in_sizes, int n_in,
                              void* d_out, int out_size)
{
    const float* rays_o  = (const float*)d_in[0];
    const float* rays_d  = (const float*)d_in[1];
    const float* xyz     = (const float*)d_in[2];
    const float* fdc     = (const float*)d_in[3];
    const float* opacity = (const float*)d_in[4];
    float* out = (float*)d_out;

    const int smem = NCELLS * 16 + NCELLS * 8;   // 96 KB
    static bool attr_set = false;
    if (!attr_set) {
        cudaFuncSetAttribute(gsplat_spatial_kernel,
                             cudaFuncAttributeMaxDynamicSharedMemorySize, smem);
        attr_set = true;
    }

    const int PB = (NPOINTS + 1023) / 1024;
    pre_bbox_kernel<<<PB, 1024>>>(xyz);
    pre_grid_kernel<<<1, 32>>>();
    pre_hist_kernel<<<PB, 1024>>>(xyz);
    pre_scan_kernel<<<1, 1024>>>();
    pre_scatter_kernel<<<PB, 1024>>>(xyz);
    gsplat_spatial_kernel<<<BATCH / WPB, TPB, smem>>>(
        rays_o, rays_d, xyz, fdc, opacity, out);
}

// round 9
// speedup vs baseline: 2.7162x; 1.5569x over previous
#include <cuda_runtime.h>
#include <math.h>

#define NPOINTS 100000
#define BATCH   4096
#define KSEL    10
#define GRIDC   16
#define NCELLS  (GRIDC*GRIDC*GRIDC)
#define FULLMASK 0xffffffffu
#define WPB     8
#define TPB     256
#define NBEST   4
#define SEEDB   4              // 4*32 = 128 seeds
#define SEEDSTR 781            // max idx 127*781 = 99187

// ---- device scratch (static: no allocations) ----
__device__ int    g_cnt[NCELLS];
__device__ int    g_off[NCELLS];
__device__ int    g_cur[NCELLS];
__device__ float4 g_pts[NPOINTS];        // (x, y, z, |p|^2), cell-sorted
__device__ int    g_sid[NPOINTS];
__device__ float4 g_cellmeta[NCELLS];    // (cx, cy, cz, |c|^2 or +INF if empty)
__device__ int    g_bbmin[3] = {0x7fffffff, 0x7fffffff, 0x7fffffff};
__device__ int    g_bbmax[3] = {0x80000000, 0x80000000, 0x80000000};

static __device__ __forceinline__ int f2ord(float f) {
    int i = __float_as_int(f);
    return (i >= 0) ? i : (i ^ 0x7fffffff);
}
static __device__ __forceinline__ float ord2f(int i) {
    return __int_as_float((i >= 0) ? i : (i ^ 0x7fffffff));
}
static __device__ __forceinline__ float sigmoidf_(float x) {
    return 1.0f / (1.0f + expf(-x));
}
// grid constants recomputed redundantly (avoids a dependency launch)
static __device__ __forceinline__ void grid_consts(float* lo, float* invc, float* cs) {
    #pragma unroll
    for (int a = 0; a < 3; a++) {
        float l = ord2f(g_bbmin[a]) - 1e-5f;
        float h = ord2f(g_bbmax[a]) + 1e-5f;
        float c = fmaxf((h - l) / GRIDC, 1e-6f);
        lo[a] = l; cs[a] = c; invc[a] = 1.0f / c;
    }
}

#define INSERT(kv, ki)                                                   \
    do { float _v = (kv); int _i = (ki);                                 \
        _Pragma("unroll")                                                \
        for (int _j = 0; _j < KSEL; _j++) {                              \
            if (_v < hd[_j]) {                                           \
                float _tv = hd[_j]; hd[_j] = _v; _v = _tv;               \
                int _ti = hix[_j]; hix[_j] = _i; _i = _ti;               \
            }                                                            \
        }                                                                \
    } while (0)

#define SCAN_CELL(offv, cntv)                                            \
    for (int g0 = 0; g0 < (cntv); g0 += 32) {                            \
        float key = POSINF;                                              \
        if (g0 + lane < (cntv)) {                                        \
            float4 p = __ldg(&g_pts[(offv) + g0 + lane]);                \
            key = fmaf(p.x, ax, fmaf(p.y, ay, fmaf(p.z, az, p.w)));      \
        }                                                                \
        unsigned im = __ballot_sync(FULLMASK, key < thr);                \
        while (im) {                                                     \
            int is = __ffs(im) - 1;                                      \
            im &= im - 1;                                                \
            float kv = __shfl_sync(FULLMASK, key, is);                   \
            if (kv < thr) {                                              \
                int pid = __ldg(&g_sid[(offv) + g0 + is]);               \
                bool dup = false;                                        \
                _Pragma("unroll")                                        \
                for (int j = 0; j < KSEL; j++) dup |= (hix[j] == pid);   \
                if (!dup) { INSERT(kv, pid); thr = hd[KSEL-1]; }         \
            }                                                            \
        }                                                                \
    }

// ---------------------------------------------------------------------------
// Preprocessing (4 launches)
// ---------------------------------------------------------------------------
__global__ void pre_bbox_kernel(const float* __restrict__ xyz) {
    int i = blockIdx.x * blockDim.x + threadIdx.x;
    if (i < NCELLS) g_cnt[i] = 0;
    int mn0, mn1, mn2, mx0, mx1, mx2;
    if (i < NPOINTS) {
        mn0 = mx0 = f2ord(xyz[3*i+0]);
        mn1 = mx1 = f2ord(xyz[3*i+1]);
        mn2 = mx2 = f2ord(xyz[3*i+2]);
    } else {
        mn0 = mn1 = mn2 = 0x7fffffff;
        mx0 = mx1 = mx2 = 0x80000000;
    }
    mn0 = __reduce_min_sync(FULLMASK, mn0);
    mn1 = __reduce_min_sync(FULLMASK, mn1);
    mn2 = __reduce_min_sync(FULLMASK, mn2);
    mx0 = __reduce_max_sync(FULLMASK, mx0);
    mx1 = __reduce_max_sync(FULLMASK, mx1);
    mx2 = __reduce_max_sync(FULLMASK, mx2);
    if ((threadIdx.x & 31) == 0) {
        atomicMin(&g_bbmin[0], mn0); atomicMax(&g_bbmax[0], mx0);
        atomicMin(&g_bbmin[1], mn1); atomicMax(&g_bbmax[1], mx1);
        atomicMin(&g_bbmin[2], mn2); atomicMax(&g_bbmax[2], mx2);
    }
}

static __device__ __forceinline__ int cell_of(float x, float y, float z,
                                              const float* lo, const float* invc) {
    int ix = min(GRIDC-1, max(0, (int)((x - lo[0]) * invc[0])));
    int iy = min(GRIDC-1, max(0, (int)((y - lo[1]) * invc[1])));
    int iz = min(GRIDC-1, max(0, (int)((z - lo[2]) * invc[2])));
    return (iz * GRIDC + iy) * GRIDC + ix;
}

__global__ void pre_hist_kernel(const float* __restrict__ xyz) {
    int i = blockIdx.x * blockDim.x + threadIdx.x;
    if (i >= NPOINTS) return;
    float lo[3], invc[3], cs[3];
    grid_consts(lo, invc, cs);
    atomicAdd(&g_cnt[cell_of(xyz[3*i], xyz[3*i+1], xyz[3*i+2], lo, invc)], 1);
}

__global__ __launch_bounds__(1024)
void pre_scan_kernel() {
    __shared__ int ssum[1024];
    float lo[3], invc[3], cs[3];
    grid_consts(lo, invc, cs);
    int t = threadIdx.x;
    int v0 = g_cnt[t*4+0], v1 = g_cnt[t*4+1], v2 = g_cnt[t*4+2], v3 = g_cnt[t*4+3];
    int s = v0 + v1 + v2 + v3;
    ssum[t] = s;
    __syncthreads();
    for (int off = 1; off < 1024; off <<= 1) {
        int x = (t >= off) ? ssum[t - off] : 0;
        __syncthreads();
        ssum[t] += x;
        __syncthreads();
    }
    int excl = ssum[t] - s;
    g_off[t*4+0] = excl;            g_cur[t*4+0] = excl;
    g_off[t*4+1] = excl + v0;       g_cur[t*4+1] = excl + v0;
    g_off[t*4+2] = excl + v0+v1;    g_cur[t*4+2] = excl + v0+v1;
    g_off[t*4+3] = excl + v0+v1+v2; g_cur[t*4+3] = excl + v0+v1+v2;
    const float POSINF = __int_as_float(0x7f800000);
    for (int c = t; c < NCELLS; c += 1024) {
        int ix = c & (GRIDC-1), iy = (c >> 4) & (GRIDC-1), iz = c >> 8;
        float gx = lo[0] + (ix + 0.5f) * cs[0];
        float gy = lo[1] + (iy + 0.5f) * cs[1];
        float gz = lo[2] + (iz + 0.5f) * cs[2];
        // empty cells poisoned to +INF: invisible to argmin AND to the sweep
        float gg = (g_cnt[c] > 0) ? (gx*gx + gy*gy + gz*gz) : POSINF;
        g_cellmeta[c] = make_float4(gx, gy, gz, gg);
    }
}

__global__ void pre_scatter_kernel(const float* __restrict__ xyz) {
    int i = blockIdx.x * blockDim.x + threadIdx.x;
    if (i >= NPOINTS) return;
    float lo[3], invc[3], cs[3];
    grid_consts(lo, invc, cs);
    float x = xyz[3*i], y = xyz[3*i+1], z = xyz[3*i+2];
    int c = cell_of(x, y, z, lo, invc);
    int pos = atomicAdd(&g_cur[c], 1);
    g_pts[pos] = make_float4(x, y, z, fmaf(x, x, fmaf(y, y, z*z)));
    g_sid[pos] = i;
}

// ---------------------------------------------------------------------------
// Main: one warp per ray; seed -> 4 best occupied cells -> conservative sweep
// ---------------------------------------------------------------------------
__global__ __launch_bounds__(TPB, 3)
void gsplat_spatial_kernel(const float* __restrict__ rays_o,
                           const float* __restrict__ rays_d,
                           const float* __restrict__ xyz,
                           const float* __restrict__ fdc,
                           const float* __restrict__ opacity,
                           float* __restrict__ out)
{
    __shared__ int2 soc[NCELLS];   // (off, cnt) per cell — 32 KB
    const int tid  = threadIdx.x;
    const int lane = tid & 31;
    const int wid  = tid >> 5;
    const int ray  = blockIdx.x * WPB + wid;
    const float POSINF = __int_as_float(0x7f800000);

    for (int i = tid; i < NCELLS; i += TPB)
        soc[i] = make_int2(g_off[i], g_cnt[i]);
    __syncthreads();

    float lo_[3], invc_[3], cs_[3];
    grid_consts(lo_, invc_, cs_);
    const float R = 0.5f * sqrtf(cs_[0]*cs_[0] + cs_[1]*cs_[1] + cs_[2]*cs_[2]);

    float ox = rays_o[3*ray+0], oy = rays_o[3*ray+1], oz = rays_o[3*ray+2];
    float dx = rays_d[3*ray+0], dy = rays_d[3*ray+1], dz = rays_d[3*ray+2];
    float cx = fmaf(dx, 3.0f, ox);
    float cy = fmaf(dy, 3.0f, oy);
    float cz = fmaf(dz, 3.0f, oz);
    float ax = -2.0f*cx, ay = -2.0f*cy, az = -2.0f*cz;
    float cn2 = cx*cx + cy*cy + cz*cz;

    float hd[KSEL]; int hix[KSEL];
    #pragma unroll
    for (int j = 0; j < KSEL; j++) { hd[j] = POSINF; hix[j] = -1; }
    float thr = POSINF;

    // ---- seed: 128 strided samples ----
    float skey[SEEDB];
    #pragma unroll
    for (int it = 0; it < SEEDB; it++) {
        int p = (it * 32 + lane) * SEEDSTR;
        float px = __ldg(&xyz[3*p]), py = __ldg(&xyz[3*p+1]), pz = __ldg(&xyz[3*p+2]);
        float pw = fmaf(px, px, fmaf(py, py, pz*pz));
        skey[it] = fmaf(px, ax, fmaf(py, ay, fmaf(pz, az, pw)));
    }
    #pragma unroll
    for (int it = 0; it < SEEDB; it++) {
        unsigned m = __ballot_sync(FULLMASK, skey[it] < thr);
        while (m) {
            int src = __ffs(m) - 1;
            m &= m - 1;
            float kv = __shfl_sync(FULLMASK, skey[it], src);
            if (kv < thr) { INSERT(kv, (it * 32 + src) * SEEDSTR); thr = hd[KSEL-1]; }
        }
    }

    // ---- best-first: NBEST successive lex-argmin picks, scanned immediately ----
    float pk = -POSINF; int pi = -1;     // lex cursor over (key, cellidx)
    for (int pass = 0; pass < NBEST; pass++) {
        float bk = POSINF; int bi = -1;
        for (int cb = 0; cb < NCELLS; cb += 32) {
            float4 m4 = __ldg(&g_cellmeta[cb + lane]);
            float gk = fmaf(m4.x, ax, fmaf(m4.y, ay, fmaf(m4.z, az, m4.w)));
            int ci = cb + lane;
            bool ok = (gk > pk) || (gk == pk && ci > pi);
            if (ok && (gk < bk || (gk == bk && ci < bi))) { bk = gk; bi = ci; }
        }
        #pragma unroll
        for (int off = 16; off; off >>= 1) {
            float ov = __shfl_xor_sync(FULLMASK, bk, off);
            int   oc = __shfl_xor_sync(FULLMASK, bi, off);
            if (ov < bk || (ov == bk && oc < bi)) { bk = ov; bi = oc; }
        }
        if (bi < 0) break;               // fewer occupied cells than NBEST
        int2 oc = soc[bi];
        SCAN_CELL(oc.x, oc.y);
        pk = bk; pi = bi;
    }
    const float k4 = pk; const int i4 = pi;

    float T = sqrtf(fmaxf(thr + cn2, 0.0f));
    float thr2 = thr + fmaf(2.0f * T, R, R * R);

    // ---- conservative sweep (empty cells have key=+INF: auto-skipped) ----
    for (int cb = 0; cb < NCELLS; cb += 32) {
        float4 m4 = __ldg(&g_cellmeta[cb + lane]);
        float gk = fmaf(m4.x, ax, fmaf(m4.y, ay, fmaf(m4.z, az, m4.w)));
        int ci = cb + lane;
        bool fresh = (gk > k4) || (gk == k4 && ci > i4);   // not among the NBEST
        unsigned pm = __ballot_sync(FULLMASK, fresh && (gk < thr2));
        while (pm) {
            int src = __ffs(pm) - 1;
            pm &= pm - 1;
            float ck = __shfl_sync(FULLMASK, gk, src);
            if (ck < thr2) {                   // re-check vs tightened thr2
                int2 oc = soc[cb + src];       // warp-uniform -> LDS broadcast
                SCAN_CELL(oc.x, oc.y);
                T = sqrtf(fmaxf(thr + cn2, 0.0f));
                thr2 = thr + fmaf(2.0f * T, R, R * R);
            }
        }
    }

    // ---- epilogue (lane 0; all lanes hold identical heaps) ----
    if (lane == 0) {
        float ws = 0.f, s0 = 0.f, s1 = 0.f, s2 = 0.f;
        #pragma unroll
        for (int k = 0; k < KSEL; k++) {
            float dist = sqrtf(fmaxf(hd[k] + cn2, 0.0f));
            int id = hix[k];
            float op = opacity[id];
            float w = expf(-0.1f * dist) * sigmoidf_(op);
            ws += w;
            s0 = fmaf(w, sigmoidf_(fdc[3*id+0]), s0);
            s1 = fmaf(w, sigmoidf_(fdc[3*id+1]), s1);
            s2 = fmaf(w, sigmoidf_(fdc[3*id+2]), s2);
        }
        float inv = 1.0f / (ws + 1e-8f);
        out[3*ray+0] = s0 * inv;
        out[3*ray+1] = s1 * inv;
        out[3*ray+2] = s2 * inv;
    }
}

extern "C" void kernel_launch(void* const* d_in, const int* in_sizes, int n_in,
                              void* d_out, int out_size)
{
    const float* rays_o  = (const float*)d_in[0];
    const float* rays_d  = (const float*)d_in[1];
    const float* xyz     = (const float*)d_in[2];
    const float* fdc     = (const float*)d_in[3];
    const float* opacity = (const float*)d_in[4];
    float* out = (float*)d_out;

    const int PB = (NPOINTS + 1023) / 1024;
    pre_bbox_kernel<<<PB, 1024>>>(xyz);
    pre_hist_kernel<<<PB, 1024>>>(xyz);
    pre_scan_kernel<<<1, 1024>>>();
    pre_scatter_kernel<<<PB, 1024>>>(xyz);
    gsplat_spatial_kernel<<<BATCH / WPB, TPB>>>(
        rays_o, rays_d, xyz, fdc, opacity, out);
}

// round 11
// speedup vs baseline: 3.1477x; 1.1589x over previous
#include <cuda_runtime.h>
#include <math.h>

#define NPOINTS 100000
#define BATCH   4096
#define KSEL    10
#define GRIDC   16
#define NCELLS  (GRIDC*GRIDC*GRIDC)
#define NCHUNK  832                 // ceil(100000/128)
#define PTSPAD  (NCHUNK*128)        // 106496
#define FULLMASK 0xffffffffu
#define WPB     8
#define TPB     256
#define SEEDSTR 781                 // 127*781 = 99187 < NPOINTS

// ---- device scratch (static: no allocations) ----
__device__ int    g_cnt[NCELLS];
__device__ int    g_off[NCELLS];
__device__ int    g_cur[NCELLS];
__device__ float4 g_pts[PTSPAD];     // (x,y,z,|p|^2) cell-sorted; pads have w=+INF
__device__ int    g_sid[PTSPAD];
__device__ float4 g_cmeta[NCHUNK];   // chunk centroid (x,y,z,|c|^2); +INF if empty
__device__ float  g_crad[NCHUNK];    // chunk bounding radius
__device__ int    g_bbmin[3] = {0x7fffffff, 0x7fffffff, 0x7fffffff};
__device__ int    g_bbmax[3] = {0x80000000, 0x80000000, 0x80000000};

static __device__ __forceinline__ int f2ord(float f) {
    int i = __float_as_int(f);
    return (i >= 0) ? i : (i ^ 0x7fffffff);
}
static __device__ __forceinline__ float ord2f(int i) {
    return __int_as_float((i >= 0) ? i : (i ^ 0x7fffffff));
}
static __device__ __forceinline__ float sigmoidf_(float x) {
    return 1.0f / (1.0f + expf(-x));
}
static __device__ __forceinline__ void grid_consts(float* lo, float* invc, float* cs) {
    #pragma unroll
    for (int a = 0; a < 3; a++) {
        float l = ord2f(g_bbmin[a]) - 1e-5f;
        float h = ord2f(g_bbmax[a]) + 1e-5f;
        float c = fmaxf((h - l) / GRIDC, 1e-6f);
        lo[a] = l; cs[a] = c; invc[a] = 1.0f / c;
    }
}

#define INSERT2(hdv, hiv, kv, ki)                                        \
    do { float _v = (kv); int _i = (ki);                                 \
        _Pragma("unroll")                                                \
        for (int _j = 0; _j < KSEL; _j++) {                              \
            if (_v < hdv[_j]) {                                          \
                float _tv = hdv[_j]; hdv[_j] = _v; _v = _tv;             \
                int _ti = hiv[_j]; hiv[_j] = _i; _i = _ti;               \
            }                                                            \
        }                                                                \
    } while (0)

// ---------------------------------------------------------------------------
// Preprocessing (5 launches)
// ---------------------------------------------------------------------------
__global__ void pre_bbox_kernel(const float* __restrict__ xyz) {
    int i = blockIdx.x * blockDim.x + threadIdx.x;
    if (i < NCELLS) g_cnt[i] = 0;
    int mn0, mn1, mn2, mx0, mx1, mx2;
    if (i < NPOINTS) {
        mn0 = mx0 = f2ord(xyz[3*i+0]);
        mn1 = mx1 = f2ord(xyz[3*i+1]);
        mn2 = mx2 = f2ord(xyz[3*i+2]);
    } else {
        mn0 = mn1 = mn2 = 0x7fffffff;
        mx0 = mx1 = mx2 = 0x80000000;
    }
    mn0 = __reduce_min_sync(FULLMASK, mn0);
    mn1 = __reduce_min_sync(FULLMASK, mn1);
    mn2 = __reduce_min_sync(FULLMASK, mn2);
    mx0 = __reduce_max_sync(FULLMASK, mx0);
    mx1 = __reduce_max_sync(FULLMASK, mx1);
    mx2 = __reduce_max_sync(FULLMASK, mx2);
    if ((threadIdx.x & 31) == 0) {
        atomicMin(&g_bbmin[0], mn0); atomicMax(&g_bbmax[0], mx0);
        atomicMin(&g_bbmin[1], mn1); atomicMax(&g_bbmax[1], mx1);
        atomicMin(&g_bbmin[2], mn2); atomicMax(&g_bbmax[2], mx2);
    }
}

static __device__ __forceinline__ int cell_of(float x, float y, float z,
                                              const float* lo, const float* invc) {
    int ix = min(GRIDC-1, max(0, (int)((x - lo[0]) * invc[0])));
    int iy = min(GRIDC-1, max(0, (int)((y - lo[1]) * invc[1])));
    int iz = min(GRIDC-1, max(0, (int)((z - lo[2]) * invc[2])));
    return (iz * GRIDC + iy) * GRIDC + ix;
}

__global__ void pre_hist_kernel(const float* __restrict__ xyz) {
    int i = blockIdx.x * blockDim.x + threadIdx.x;
    if (i >= NPOINTS) return;
    float lo[3], invc[3], cs[3];
    grid_consts(lo, invc, cs);
    atomicAdd(&g_cnt[cell_of(xyz[3*i], xyz[3*i+1], xyz[3*i+2], lo, invc)], 1);
}

__global__ __launch_bounds__(1024)
void pre_scan_kernel() {
    __shared__ int ssum[1024];
    int t = threadIdx.x;
    int v0 = g_cnt[t*4+0], v1 = g_cnt[t*4+1], v2 = g_cnt[t*4+2], v3 = g_cnt[t*4+3];
    int s = v0 + v1 + v2 + v3;
    ssum[t] = s;
    __syncthreads();
    for (int off = 1; off < 1024; off <<= 1) {
        int x = (t >= off) ? ssum[t - off] : 0;
        __syncthreads();
        ssum[t] += x;
        __syncthreads();
    }
    int excl = ssum[t] - s;
    g_cur[t*4+0] = excl;
    g_cur[t*4+1] = excl + v0;
    g_cur[t*4+2] = excl + v0 + v1;
    g_cur[t*4+3] = excl + v0 + v1 + v2;
}

__global__ void pre_scatter_kernel(const float* __restrict__ xyz) {
    int i = blockIdx.x * blockDim.x + threadIdx.x;
    if (i >= NPOINTS) return;
    float lo[3], invc[3], cs[3];
    grid_consts(lo, invc, cs);
    float x = xyz[3*i], y = xyz[3*i+1], z = xyz[3*i+2];
    int c = cell_of(x, y, z, lo, invc);
    int pos = atomicAdd(&g_cur[c], 1);
    g_pts[pos] = make_float4(x, y, z, fmaf(x, x, fmaf(y, y, z*z)));
    g_sid[pos] = i;
}

// One warp per chunk: fill pads, compute centroid + bounding radius.
__global__ void pre_chunkmeta_kernel() {
    int w    = (blockIdx.x * blockDim.x + threadIdx.x) >> 5;
    int lane = threadIdx.x & 31;
    if (w >= NCHUNK) return;
    const float POSINF = __int_as_float(0x7f800000);
    int base = w << 7;

    float4 v[4];
    #pragma unroll
    for (int i = 0; i < 4; i++) {
        int idx = base + i * 32 + lane;
        if (idx < NPOINTS) {
            v[i] = g_pts[idx];
        } else {
            v[i] = make_float4(0.f, 0.f, 0.f, POSINF);
            g_pts[idx] = v[i];
            g_sid[idx] = 0;
        }
    }
    int nreal = min(128, max(0, NPOINTS - base));
    if (nreal == 0) {
        if (lane == 0) { g_cmeta[w] = make_float4(0.f, 0.f, 0.f, POSINF); g_crad[w] = 0.f; }
        return;
    }
    float sx = 0.f, sy = 0.f, sz = 0.f;
    #pragma unroll
    for (int i = 0; i < 4; i++) {
        if (base + i * 32 + lane < NPOINTS) { sx += v[i].x; sy += v[i].y; sz += v[i].z; }
    }
    #pragma unroll
    for (int off = 16; off; off >>= 1) {
        sx += __shfl_xor_sync(FULLMASK, sx, off);
        sy += __shfl_xor_sync(FULLMASK, sy, off);
        sz += __shfl_xor_sync(FULLMASK, sz, off);
    }
    float inv = 1.0f / (float)nreal;
    float cx = sx * inv, cy = sy * inv, cz = sz * inv;
    float md = 0.f;
    #pragma unroll
    for (int i = 0; i < 4; i++) {
        if (base + i * 32 + lane < NPOINTS) {
            float ddx = v[i].x - cx, ddy = v[i].y - cy, ddz = v[i].z - cz;
            md = fmaxf(md, fmaf(ddx, ddx, fmaf(ddy, ddy, ddz * ddz)));
        }
    }
    #pragma unroll
    for (int off = 16; off; off >>= 1)
        md = fmaxf(md, __shfl_xor_sync(FULLMASK, md, off));
    if (lane == 0) {
        g_cmeta[w] = make_float4(cx, cy, cz, fmaf(cx, cx, fmaf(cy, cy, cz * cz)));
        g_crad[w] = sqrtf(md);
    }
}

// ---------------------------------------------------------------------------
// Main: screened linear sweep; one warp handles 2 rays; heap replicated in regs
// ---------------------------------------------------------------------------
// exact k-th (k>=10) smallest of the warp's 128 values (destructive on a[])
static __device__ __forceinline__ float tenth_min(float* a) {
    const float POSINF = __int_as_float(0x7f800000);
    float wm = POSINF;
    for (int rnd = 0; rnd < KSEL; rnd++) {
        float lm = fminf(fminf(a[0], a[1]), fminf(a[2], a[3]));
        #pragma unroll
        for (int off = 16; off; off >>= 1)
            lm = fminf(lm, __shfl_xor_sync(FULLMASK, lm, off));
        wm = lm;
        #pragma unroll
        for (int i = 0; i < 4; i++) if (a[i] == wm) a[i] = POSINF;
    }
    return wm;
}

__global__ __launch_bounds__(TPB)
void gsplat_sweep_kernel(const float* __restrict__ rays_o,
                         const float* __restrict__ rays_d,
                         const float* __restrict__ fdc,
                         const float* __restrict__ opacity,
                         float* __restrict__ out)
{
    const int lane = threadIdx.x & 31;
    const int wid  = threadIdx.x >> 5;
    const int ray0 = (blockIdx.x * WPB + wid) * 2;
    const int ray1 = ray0 + 1;
    const float POSINF = __int_as_float(0x7f800000);

    float ax0, ay0, az0, cn20, ax1, ay1, az1, cn21;
    {
        float ox = rays_o[3*ray0+0], oy = rays_o[3*ray0+1], oz = rays_o[3*ray0+2];
        float dx = rays_d[3*ray0+0], dy = rays_d[3*ray0+1], dz = rays_d[3*ray0+2];
        float cx = fmaf(dx, 3.0f, ox), cy = fmaf(dy, 3.0f, oy), cz = fmaf(dz, 3.0f, oz);
        ax0 = -2.0f*cx; ay0 = -2.0f*cy; az0 = -2.0f*cz;
        cn20 = cx*cx + cy*cy + cz*cz;
        ox = rays_o[3*ray1+0]; oy = rays_o[3*ray1+1]; oz = rays_o[3*ray1+2];
        dx = rays_d[3*ray1+0]; dy = rays_d[3*ray1+1]; dz = rays_d[3*ray1+2];
        cx = fmaf(dx, 3.0f, ox); cy = fmaf(dy, 3.0f, oy); cz = fmaf(dz, 3.0f, oz);
        ax1 = -2.0f*cx; ay1 = -2.0f*cy; az1 = -2.0f*cz;
        cn21 = cx*cx + cy*cy + cz*cz;
    }

    float hd0[KSEL], hd1[KSEL]; int hi0[KSEL], hi1[KSEL];
    #pragma unroll
    for (int j = 0; j < KSEL; j++) { hd0[j] = POSINF; hd1[j] = POSINF; hi0[j] = 0; hi1[j] = 0; }

    // ---- seed thresholds from 128 strided samples (thr only; NOT inserted) ----
    float s0a[4], s1a[4];
    #pragma unroll
    for (int it = 0; it < 4; it++) {
        int p = (it * 32 + lane) * SEEDSTR;
        float4 q = __ldg(&g_pts[p]);
        s0a[it] = fmaf(q.x, ax0, fmaf(q.y, ay0, fmaf(q.z, az0, q.w)));
        s1a[it] = fmaf(q.x, ax1, fmaf(q.y, ay1, fmaf(q.z, az1, q.w)));
    }
    float thr0 = tenth_min(s0a);      // >= true d10^2 for ray0 (conservative)
    float thr1 = tenth_min(s1a);
    float t20 = 2.0f * sqrtf(fmaxf(thr0 + cn20, 0.0f));
    float t21 = 2.0f * sqrtf(fmaxf(thr1 + cn21, 0.0f));

    // ---- screened linear sweep over all chunks ----
    for (int cb = 0; cb < NCHUNK; cb += 32) {
        float4 m  = __ldg(&g_cmeta[cb + lane]);
        float rad = __ldg(&g_crad[cb + lane]);
        float rr  = rad * rad;
        float kc0 = fmaf(m.x, ax0, fmaf(m.y, ay0, fmaf(m.z, az0, m.w)));
        float kc1 = fmaf(m.x, ax1, fmaf(m.y, ay1, fmaf(m.z, az1, m.w)));
        bool p0 = kc0 <= thr0 + fmaf(t20, rad, rr);
        bool p1 = kc1 <= thr1 + fmaf(t21, rad, rr);
        unsigned pm = __ballot_sync(FULLMASK, p0 | p1);
        while (pm) {
            int src = __ffs(pm) - 1;
            pm &= pm - 1;
            int pb = (cb + src) << 7;          // chunk base point index
            #pragma unroll
            for (int it = 0; it < 4; it++) {
                int ib = pb + it * 32;
                float4 p = __ldg(&g_pts[ib + lane]);
                float k0 = fmaf(p.x, ax0, fmaf(p.y, ay0, fmaf(p.z, az0, p.w)));
                float k1 = fmaf(p.x, ax1, fmaf(p.y, ay1, fmaf(p.z, az1, p.w)));
                unsigned m0 = __ballot_sync(FULLMASK, k0 <= thr0);
                while (m0) {
                    int is = __ffs(m0) - 1;
                    m0 &= m0 - 1;
                    float kv = __shfl_sync(FULLMASK, k0, is);
                    if (kv <= thr0) {
                        INSERT2(hd0, hi0, kv, ib + is);
                        thr0 = fminf(thr0, hd0[KSEL-1]);
                    }
                }
                unsigned m1 = __ballot_sync(FULLMASK, k1 <= thr1);
                while (m1) {
                    int is = __ffs(m1) - 1;
                    m1 &= m1 - 1;
                    float kv = __shfl_sync(FULLMASK, k1, is);
                    if (kv <= thr1) {
                        INSERT2(hd1, hi1, kv, ib + is);
                        thr1 = fminf(thr1, hd1[KSEL-1]);
                    }
                }
            }
            t20 = 2.0f * sqrtf(fmaxf(thr0 + cn20, 0.0f));
            t21 = 2.0f * sqrtf(fmaxf(thr1 + cn21, 0.0f));
        }
    }

    // ---- epilogue (lane 0; all lanes hold identical heaps) ----
    if (lane == 0) {
        #define EPILOG(hdv, hiv, cn2v, rayv)                                   \
        do {                                                                   \
            float ws = 0.f, e0 = 0.f, e1 = 0.f, e2 = 0.f;                      \
            _Pragma("unroll")                                                  \
            for (int k = 0; k < KSEL; k++) {                                   \
                float dist = sqrtf(fmaxf(hdv[k] + cn2v, 0.0f));                \
                int id = __ldg(&g_sid[hiv[k]]);                                \
                float w = expf(-0.1f * dist) * sigmoidf_(opacity[id]);         \
                ws += w;                                                       \
                e0 = fmaf(w, sigmoidf_(fdc[3*id+0]), e0);                      \
                e1 = fmaf(w, sigmoidf_(fdc[3*id+1]), e1);                      \
                e2 = fmaf(w, sigmoidf_(fdc[3*id+2]), e2);                      \
            }                                                                  \
            float inv = 1.0f / (ws + 1e-8f);                                   \
            out[3*(rayv)+0] = e0 * inv;                                        \
            out[3*(rayv)+1] = e1 * inv;                                        \
            out[3*(rayv)+2] = e2 * inv;                                        \
        } while (0)
        EPILOG(hd0, hi0, cn20, ray0);
        EPILOG(hd1, hi1, cn21, ray1);
        #undef EPILOG
    }
}

extern "C" void kernel_launch(void* const* d_in, const int* in_sizes, int n_in,
                              void* d_out, int out_size)
{
    const float* rays_o  = (const float*)d_in[0];
    const float* rays_d  = (const float*)d_in[1];
    const float* xyz     = (const float*)d_in[2];
    const float* fdc     = (const float*)d_in[3];
    const float* opacity = (const float*)d_in[4];
    float* out = (float*)d_out;

    const int PB = (NPOINTS + 1023) / 1024;
    pre_bbox_kernel<<<PB, 1024>>>(xyz);
    pre_hist_kernel<<<PB, 1024>>>(xyz);
    pre_scan_kernel<<<1, 1024>>>();
    pre_scatter_kernel<<<PB, 1024>>>(xyz);
    pre_chunkmeta_kernel<<<(NCHUNK * 32 + TPB - 1) / TPB, TPB>>>();
    gsplat_sweep_kernel<<<BATCH / (WPB * 2), TPB>>>(
        rays_o, rays_d, fdc, opacity, out);
}

// round 12
// speedup vs baseline: 5.9895x; 1.9028x over previous
#include <cuda_runtime.h>
#include <math.h>

#define NPOINTS 100000
#define BATCH   4096
#define KSEL    10
#define GRIDC   16
#define NCELLS  (GRIDC*GRIDC*GRIDC)
#define NCHUNK  782                 // ceil(100000/128)
#define NCHPAD  800                 // padded chunk count (mult of 32)
#define PTSPAD  (NCHUNK*128)        // 100096
#define FULLMASK 0xffffffffu
#define WPB     8
#define TPB     256
#define SEEDSTR 97                  // 1023*97 = 99231 < NPOINTS

// fixed grid bounds: data ~ N(0,0.1); cell_of clamps, so ANY bounds are correct.
#define GLO  (-0.75f)
#define GCS  (1.5f / GRIDC)
#define GINV (GRIDC / 1.5f)

// ---- device scratch (static: no allocations) ----
__device__ int    g_cnt[NCELLS];
__device__ int    g_cur[NCELLS];
__device__ float4 g_pts[PTSPAD];     // (x,y,z,|p|^2) cell-sorted; pads w=+INF
__device__ int    g_sid[PTSPAD];
__device__ float4 g_cmeta[NCHPAD];   // chunk centroid (x,y,z,|c|^2); w=+INF if empty
__device__ float  g_crad[NCHPAD];

static __device__ __forceinline__ float sigmoidf_(float x) {
    return 1.0f / (1.0f + expf(-x));
}
static __device__ __forceinline__ int cell_of(float x, float y, float z) {
    int ix = min(GRIDC-1, max(0, (int)((x - GLO) * GINV)));
    int iy = min(GRIDC-1, max(0, (int)((y - GLO) * GINV)));
    int iz = min(GRIDC-1, max(0, (int)((z - GLO) * GINV)));
    return (iz * GRIDC + iy) * GRIDC + ix;
}

#define INSERT2(hdv, hiv, kv, ki)                                        \
    do { float _v = (kv); int _i = (ki);                                 \
        _Pragma("unroll")                                                \
        for (int _j = 0; _j < KSEL; _j++) {                              \
            if (_v < hdv[_j]) {                                          \
                float _tv = hdv[_j]; hdv[_j] = _v; _v = _tv;             \
                int _ti = hiv[_j]; hiv[_j] = _i; _i = _ti;               \
            }                                                            \
        }                                                                \
    } while (0)

// lane-local sorted insert (values only, ascending)
#define SORT10_INS(arr, v)                                               \
    do { float _v = (v);                                                 \
        if (_v < arr[KSEL-1]) {                                          \
            _Pragma("unroll")                                            \
            for (int _j = 0; _j < KSEL; _j++) {                          \
                float _lo = fminf(arr[_j], _v);                          \
                float _hi = fmaxf(arr[_j], _v);                          \
                arr[_j] = _lo; _v = _hi;                                 \
            }                                                            \
        }                                                                \
    } while (0)

// ---------------------------------------------------------------------------
// Preprocessing (4 kernels; g_cnt zeroed via memset node)
// ---------------------------------------------------------------------------
__global__ void pre_hist_kernel(const float* __restrict__ xyz) {
    int i = blockIdx.x * blockDim.x + threadIdx.x;
    if (i >= NPOINTS) return;
    atomicAdd(&g_cnt[cell_of(xyz[3*i], xyz[3*i+1], xyz[3*i+2])], 1);
}

__global__ __launch_bounds__(1024)
void pre_scan_kernel() {
    __shared__ int ssum[1024];
    int t = threadIdx.x;
    int v0 = g_cnt[t*4+0], v1 = g_cnt[t*4+1], v2 = g_cnt[t*4+2], v3 = g_cnt[t*4+3];
    int s = v0 + v1 + v2 + v3;
    ssum[t] = s;
    __syncthreads();
    for (int off = 1; off < 1024; off <<= 1) {
        int x = (t >= off) ? ssum[t - off] : 0;
        __syncthreads();
        ssum[t] += x;
        __syncthreads();
    }
    int excl = ssum[t] - s;
    g_cur[t*4+0] = excl;
    g_cur[t*4+1] = excl + v0;
    g_cur[t*4+2] = excl + v0 + v1;
    g_cur[t*4+3] = excl + v0 + v1 + v2;
}

__global__ void pre_scatter_kernel(const float* __restrict__ xyz) {
    int i = blockIdx.x * blockDim.x + threadIdx.x;
    if (i >= NPOINTS) return;
    float x = xyz[3*i], y = xyz[3*i+1], z = xyz[3*i+2];
    int pos = atomicAdd(&g_cur[cell_of(x, y, z)], 1);
    g_pts[pos] = make_float4(x, y, z, fmaf(x, x, fmaf(y, y, z*z)));
    g_sid[pos] = i;
}

// one warp per (padded) chunk: fill pads, centroid + bounding radius
__global__ void pre_chunkmeta_kernel() {
    int w    = (blockIdx.x * blockDim.x + threadIdx.x) >> 5;
    int lane = threadIdx.x & 31;
    if (w >= NCHPAD) return;
    const float POSINF = __int_as_float(0x7f800000);
    if (w >= NCHUNK) {
        if (lane == 0) { g_cmeta[w] = make_float4(0.f, 0.f, 0.f, POSINF); g_crad[w] = 0.f; }
        return;
    }
    int base = w << 7;
    float4 v[4];
    #pragma unroll
    for (int i = 0; i < 4; i++) {
        int idx = base + i * 32 + lane;
        if (idx < NPOINTS) {
            v[i] = g_pts[idx];
        } else {
            v[i] = make_float4(0.f, 0.f, 0.f, POSINF);
            g_pts[idx] = v[i];
            g_sid[idx] = 0;
        }
    }
    int nreal = min(128, NPOINTS - base);
    float sx = 0.f, sy = 0.f, sz = 0.f;
    #pragma unroll
    for (int i = 0; i < 4; i++)
        if (base + i * 32 + lane < NPOINTS) { sx += v[i].x; sy += v[i].y; sz += v[i].z; }
    #pragma unroll
    for (int off = 16; off; off >>= 1) {
        sx += __shfl_xor_sync(FULLMASK, sx, off);
        sy += __shfl_xor_sync(FULLMASK, sy, off);
        sz += __shfl_xor_sync(FULLMASK, sz, off);
    }
    float inv = 1.0f / (float)nreal;
    float cx = sx * inv, cy = sy * inv, cz = sz * inv;
    float md = 0.f;
    #pragma unroll
    for (int i = 0; i < 4; i++) {
        if (base + i * 32 + lane < NPOINTS) {
            float ddx = v[i].x - cx, ddy = v[i].y - cy, ddz = v[i].z - cz;
            md = fmaxf(md, fmaf(ddx, ddx, fmaf(ddy, ddy, ddz * ddz)));
        }
    }
    #pragma unroll
    for (int off = 16; off; off >>= 1)
        md = fmaxf(md, __shfl_xor_sync(FULLMASK, md, off));
    if (lane == 0) {
        g_cmeta[w] = make_float4(cx, cy, cz, fmaf(cx, cx, fmaf(cy, cy, cz * cz)));
        g_crad[w] = sqrtf(md);
    }
}

// ---------------------------------------------------------------------------
// Main: 1024-sample seeded threshold + screened linear sweep; 2 rays/warp
// ---------------------------------------------------------------------------
__global__ __launch_bounds__(TPB)
void gsplat_sweep_kernel(const float* __restrict__ rays_o,
                         const float* __restrict__ rays_d,
                         const float* __restrict__ fdc,
                         const float* __restrict__ opacity,
                         float* __restrict__ out)
{
    const int lane = threadIdx.x & 31;
    const int wid  = threadIdx.x >> 5;
    const int ray0 = (blockIdx.x * WPB + wid) * 2;
    const int ray1 = ray0 + 1;
    const float POSINF = __int_as_float(0x7f800000);

    float ax0, ay0, az0, cn20, ax1, ay1, az1, cn21;
    {
        float ox = rays_o[3*ray0+0], oy = rays_o[3*ray0+1], oz = rays_o[3*ray0+2];
        float dx = rays_d[3*ray0+0], dy = rays_d[3*ray0+1], dz = rays_d[3*ray0+2];
        float cx = fmaf(dx, 3.0f, ox), cy = fmaf(dy, 3.0f, oy), cz = fmaf(dz, 3.0f, oz);
        ax0 = -2.0f*cx; ay0 = -2.0f*cy; az0 = -2.0f*cz;
        cn20 = cx*cx + cy*cy + cz*cz;
        ox = rays_o[3*ray1+0]; oy = rays_o[3*ray1+1]; oz = rays_o[3*ray1+2];
        dx = rays_d[3*ray1+0]; dy = rays_d[3*ray1+1]; dz = rays_d[3*ray1+2];
        cx = fmaf(dx, 3.0f, ox); cy = fmaf(dy, 3.0f, oy); cz = fmaf(dz, 3.0f, oz);
        ax1 = -2.0f*cx; ay1 = -2.0f*cy; az1 = -2.0f*cz;
        cn21 = cx*cx + cy*cy + cz*cz;
    }

    // ---- seed thr: exact 10th-min over 1024 strided samples (thr-only) ----
    float sa0[KSEL], sa1[KSEL];
    #pragma unroll
    for (int j = 0; j < KSEL; j++) { sa0[j] = POSINF; sa1[j] = POSINF; }
    for (int it = 0; it < 32; it++) {
        int p = (it * 32 + lane) * SEEDSTR;
        float4 q = __ldg(&g_pts[p]);
        float k0 = fmaf(q.x, ax0, fmaf(q.y, ay0, fmaf(q.z, az0, q.w)));
        float k1 = fmaf(q.x, ax1, fmaf(q.y, ay1, fmaf(q.z, az1, q.w)));
        SORT10_INS(sa0, k0);
        SORT10_INS(sa1, k1);
    }
    // warp 10th-min extraction: 10 rounds of (min of heads, shift consumed lanes)
    float thr0, thr1;
    {
        float m0 = 0.f, m1 = 0.f;
        #pragma unroll
        for (int rnd = 0; rnd < KSEL; rnd++) {
            float h0 = sa0[0], h1 = sa1[0];
            #pragma unroll
            for (int off = 16; off; off >>= 1) {
                h0 = fminf(h0, __shfl_xor_sync(FULLMASK, h0, off));
                h1 = fminf(h1, __shfl_xor_sync(FULLMASK, h1, off));
            }
            m0 = h0; m1 = h1;
            bool c0 = (sa0[0] == h0), c1 = (sa1[0] == h1);
            #pragma unroll
            for (int j = 0; j < KSEL-1; j++) {
                sa0[j] = c0 ? sa0[j+1] : sa0[j];
                sa1[j] = c1 ? sa1[j+1] : sa1[j];
            }
            if (c0) sa0[KSEL-1] = POSINF;
            if (c1) sa1[KSEL-1] = POSINF;
        }
        thr0 = m0; thr1 = m1;   // >= true d10^2 (sample 10th >= full-set 10th)
    }

    float hd0[KSEL], hd1[KSEL]; int hi0[KSEL], hi1[KSEL];
    #pragma unroll
    for (int j = 0; j < KSEL; j++) { hd0[j] = POSINF; hd1[j] = POSINF; hi0[j] = 0; hi1[j] = 0; }

    float t20 = 2.0f * sqrtf(fmaxf(thr0 + cn20, 0.0f));
    float t21 = 2.0f * sqrtf(fmaxf(thr1 + cn21, 0.0f));

    // ---- screened linear sweep over all chunks ----
    for (int cb = 0; cb < NCHPAD; cb += 32) {
        float4 m  = __ldg(&g_cmeta[cb + lane]);
        float rad = __ldg(&g_crad[cb + lane]);
        float rr  = rad * rad;
        float kc0 = fmaf(m.x, ax0, fmaf(m.y, ay0, fmaf(m.z, az0, m.w)));
        float kc1 = fmaf(m.x, ax1, fmaf(m.y, ay1, fmaf(m.z, az1, m.w)));
        bool p0 = kc0 <= thr0 + fmaf(t20, rad, rr);
        bool p1 = kc1 <= thr1 + fmaf(t21, rad, rr);
        unsigned pm = __ballot_sync(FULLMASK, p0 | p1);
        while (pm) {
            int src = __ffs(pm) - 1;
            pm &= pm - 1;
            int pb = (cb + src) << 7;
            // prefetch all 4 groups (MLP=4), then math
            float4 q0 = __ldg(&g_pts[pb + lane]);
            float4 q1 = __ldg(&g_pts[pb + 32 + lane]);
            float4 q2 = __ldg(&g_pts[pb + 64 + lane]);
            float4 q3 = __ldg(&g_pts[pb + 96 + lane]);
            #pragma unroll
            for (int it = 0; it < 4; it++) {
                float4 p = (it == 0) ? q0 : (it == 1) ? q1 : (it == 2) ? q2 : q3;
                int ib = pb + it * 32;
                float k0 = fmaf(p.x, ax0, fmaf(p.y, ay0, fmaf(p.z, az0, p.w)));
                float k1 = fmaf(p.x, ax1, fmaf(p.y, ay1, fmaf(p.z, az1, p.w)));
                unsigned m0 = __ballot_sync(FULLMASK, k0 <= thr0);
                while (m0) {
                    int is = __ffs(m0) - 1;
                    m0 &= m0 - 1;
                    float kv = __shfl_sync(FULLMASK, k0, is);
                    if (kv <= thr0) {
                        INSERT2(hd0, hi0, kv, ib + is);
                        thr0 = fminf(thr0, hd0[KSEL-1]);
                    }
                }
                unsigned m1 = __ballot_sync(FULLMASK, k1 <= thr1);
                while (m1) {
                    int is = __ffs(m1) - 1;
                    m1 &= m1 - 1;
                    float kv = __shfl_sync(FULLMASK, k1, is);
                    if (kv <= thr1) {
                        INSERT2(hd1, hi1, kv, ib + is);
                        thr1 = fminf(thr1, hd1[KSEL-1]);
                    }
                }
            }
            t20 = 2.0f * sqrtf(fmaxf(thr0 + cn20, 0.0f));
            t21 = 2.0f * sqrtf(fmaxf(thr1 + cn21, 0.0f));
        }
    }

    // ---- epilogue (lane 0; all lanes hold identical heaps) ----
    if (lane == 0) {
        #define EPILOG(hdv, hiv, cn2v, rayv)                                   \
        do {                                                                   \
            float ws = 0.f, e0 = 0.f, e1 = 0.f, e2 = 0.f;                      \
            _Pragma("unroll")                                                  \
            for (int k = 0; k < KSEL; k++) {                                   \
                float dist = sqrtf(fmaxf(hdv[k] + cn2v, 0.0f));                \
                int id = __ldg(&g_sid[hiv[k]]);                                \
                float w = expf(-0.1f * dist) * sigmoidf_(opacity[id]);         \
                ws += w;                                                       \
                e0 = fmaf(w, sigmoidf_(fdc[3*id+0]), e0);                      \
                e1 = fmaf(w, sigmoidf_(fdc[3*id+1]), e1);                      \
                e2 = fmaf(w, sigmoidf_(fdc[3*id+2]), e2);                      \
            }                                                                  \
            float inv = 1.0f / (ws + 1e-8f);                                   \
            out[3*(rayv)+0] = e0 * inv;                                        \
            out[3*(rayv)+1] = e1 * inv;                                        \
            out[3*(rayv)+2] = e2 * inv;                                        \
        } while (0)
        EPILOG(hd0, hi0, cn20, ray0);
        EPILOG(hd1, hi1, cn21, ray1);
        #undef EPILOG
    }
}

extern "C" void kernel_launch(void* const* d_in, const int* in_sizes, int n_in,
                              void* d_out, int out_size)
{
    const float* rays_o  = (const float*)d_in[0];
    const float* rays_d  = (const float*)d_in[1];
    const float* xyz     = (const float*)d_in[2];
    const float* fdc     = (const float*)d_in[3];
    const float* opacity = (const float*)d_in[4];
    float* out = (float*)d_out;

    void* cnt_addr = nullptr;
    cudaGetSymbolAddress(&cnt_addr, g_cnt);
    cudaMemsetAsync(cnt_addr, 0, NCELLS * sizeof(int));

    const int PB = (NPOINTS + 1023) / 1024;
    pre_hist_kernel<<<PB, 1024>>>(xyz);
    pre_scan_kernel<<<1, 1024>>>();
    pre_scatter_kernel<<<PB, 1024>>>(xyz);
    pre_chunkmeta_kernel<<<(NCHPAD * 32) / TPB, TPB>>>();
    gsplat_sweep_kernel<<<BATCH / (WPB * 2), TPB>>>(
        rays_o, rays_d, fdc, opacity, out);
}

// round 13
// speedup vs baseline: 9.3969x; 1.5689x over previous
#include <cuda_runtime.h>
#include <math.h>

#define NPOINTS 100000
#define BATCH   4096
#define KSEL    10
#define GRIDC   16
#define NCELLS  (GRIDC*GRIDC*GRIDC)
#define CHUNK   64
#define NCHUNK  1563                // ceil(100000/64)
#define NCHPAD  1568                // mult of 32
#define PTSPAD  (NCHUNK*CHUNK)     // 100032
#define FULLMASK 0xffffffffu
#define WPB     8
#define TPB     256
#define SEEDSTR 97                  // 1023*97 = 99231 < NPOINTS

// fixed grid bounds: data ~ N(0,0.1); cell_of clamps, so ANY bounds are correct.
#define GLO  (-0.75f)
#define GINV (GRIDC / 1.5f)

// ---- device scratch (static: no allocations) ----
__device__ int    g_cnt[NCELLS];
__device__ int    g_cur[NCELLS];
__device__ float4 g_pts[PTSPAD];     // (x,y,z,|p|^2) Morton-cell-sorted; pads w=+INF
__device__ int    g_sid[PTSPAD];
__device__ float4 g_cmeta[NCHPAD];   // chunk centroid (x,y,z,|c|^2); w=+INF if empty
__device__ float  g_crad[NCHPAD];

static __device__ __forceinline__ float sigmoidf_(float x) {
    return 1.0f / (1.0f + expf(-x));
}
// Morton (z-order) cell index: compact chunks -> small bounding radii
static __device__ __forceinline__ int cell_of(float x, float y, float z) {
    int ix = min(GRIDC-1, max(0, (int)((x - GLO) * GINV)));
    int iy = min(GRIDC-1, max(0, (int)((y - GLO) * GINV)));
    int iz = min(GRIDC-1, max(0, (int)((z - GLO) * GINV)));
    int m = 0;
    #pragma unroll
    for (int b = 0; b < 4; b++) {
        m |= ((ix >> b) & 1) << (3*b)
           | ((iy >> b) & 1) << (3*b + 1)
           | ((iz >> b) & 1) << (3*b + 2);
    }
    return m;
}

#define INSERT2(hdv, hiv, kv, ki)                                        \
    do { float _v = (kv); int _i = (ki);                                 \
        _Pragma("unroll")                                                \
        for (int _j = 0; _j < KSEL; _j++) {                              \
            if (_v < hdv[_j]) {                                          \
                float _tv = hdv[_j]; hdv[_j] = _v; _v = _tv;             \
                int _ti = hiv[_j]; hiv[_j] = _i; _i = _ti;               \
            }                                                            \
        }                                                                \
    } while (0)

// lane-local sorted insert (values only, ascending)
#define SORT10_INS(arr, v)                                               \
    do { float _v = (v);                                                 \
        if (_v < arr[KSEL-1]) {                                          \
            _Pragma("unroll")                                            \
            for (int _j = 0; _j < KSEL; _j++) {                          \
                float _lo = fminf(arr[_j], _v);                          \
                float _hi = fmaxf(arr[_j], _v);                          \
                arr[_j] = _lo; _v = _hi;                                 \
            }                                                            \
        }                                                                \
    } while (0)

// ---------------------------------------------------------------------------
// Preprocessing (memset + 4 kernels)
// ---------------------------------------------------------------------------
__global__ void pre_hist_kernel(const float* __restrict__ xyz) {
    int i = blockIdx.x * blockDim.x + threadIdx.x;
    if (i >= NPOINTS) return;
    atomicAdd(&g_cnt[cell_of(xyz[3*i], xyz[3*i+1], xyz[3*i+2])], 1);
}

__global__ __launch_bounds__(1024)
void pre_scan_kernel() {
    __shared__ int ssum[1024];
    int t = threadIdx.x;
    int v0 = g_cnt[t*4+0], v1 = g_cnt[t*4+1], v2 = g_cnt[t*4+2], v3 = g_cnt[t*4+3];
    int s = v0 + v1 + v2 + v3;
    ssum[t] = s;
    __syncthreads();
    for (int off = 1; off < 1024; off <<= 1) {
        int x = (t >= off) ? ssum[t - off] : 0;
        __syncthreads();
        ssum[t] += x;
        __syncthreads();
    }
    int excl = ssum[t] - s;
    g_cur[t*4+0] = excl;
    g_cur[t*4+1] = excl + v0;
    g_cur[t*4+2] = excl + v0 + v1;
    g_cur[t*4+3] = excl + v0 + v1 + v2;
}

__global__ void pre_scatter_kernel(const float* __restrict__ xyz) {
    int i = blockIdx.x * blockDim.x + threadIdx.x;
    if (i >= NPOINTS) return;
    float x = xyz[3*i], y = xyz[3*i+1], z = xyz[3*i+2];
    int pos = atomicAdd(&g_cur[cell_of(x, y, z)], 1);
    g_pts[pos] = make_float4(x, y, z, fmaf(x, x, fmaf(y, y, z*z)));
    g_sid[pos] = i;
}

// one warp per (padded) chunk of 64: fill pads, centroid + bounding radius
__global__ void pre_chunkmeta_kernel() {
    int w    = (blockIdx.x * blockDim.x + threadIdx.x) >> 5;
    int lane = threadIdx.x & 31;
    if (w >= NCHPAD) return;
    const float POSINF = __int_as_float(0x7f800000);
    if (w >= NCHUNK) {
        if (lane == 0) { g_cmeta[w] = make_float4(0.f, 0.f, 0.f, POSINF); g_crad[w] = 0.f; }
        return;
    }
    int base = w * CHUNK;
    float4 v[2];
    #pragma unroll
    for (int i = 0; i < 2; i++) {
        int idx = base + i * 32 + lane;
        if (idx < NPOINTS) {
            v[i] = g_pts[idx];
        } else {
            v[i] = make_float4(0.f, 0.f, 0.f, POSINF);
            g_pts[idx] = v[i];
            g_sid[idx] = 0;
        }
    }
    int nreal = min(CHUNK, NPOINTS - base);
    float sx = 0.f, sy = 0.f, sz = 0.f;
    #pragma unroll
    for (int i = 0; i < 2; i++)
        if (base + i * 32 + lane < NPOINTS) { sx += v[i].x; sy += v[i].y; sz += v[i].z; }
    #pragma unroll
    for (int off = 16; off; off >>= 1) {
        sx += __shfl_xor_sync(FULLMASK, sx, off);
        sy += __shfl_xor_sync(FULLMASK, sy, off);
        sz += __shfl_xor_sync(FULLMASK, sz, off);
    }
    float inv = 1.0f / (float)nreal;
    float cx = sx * inv, cy = sy * inv, cz = sz * inv;
    float md = 0.f;
    #pragma unroll
    for (int i = 0; i < 2; i++) {
        if (base + i * 32 + lane < NPOINTS) {
            float ddx = v[i].x - cx, ddy = v[i].y - cy, ddz = v[i].z - cz;
            md = fmaxf(md, fmaf(ddx, ddx, fmaf(ddy, ddy, ddz * ddz)));
        }
    }
    #pragma unroll
    for (int off = 16; off; off >>= 1)
        md = fmaxf(md, __shfl_xor_sync(FULLMASK, md, off));
    if (lane == 0) {
        g_cmeta[w] = make_float4(cx, cy, cz, fmaf(cx, cx, fmaf(cy, cy, cz * cz)));
        g_crad[w] = sqrtf(md);
    }
}

// ---------------------------------------------------------------------------
// Main: one warp per ray; 1024-sample seed threshold + screened linear sweep
// ---------------------------------------------------------------------------
__global__ __launch_bounds__(TPB)
void gsplat_sweep_kernel(const float* __restrict__ rays_o,
                         const float* __restrict__ rays_d,
                         const float* __restrict__ fdc,
                         const float* __restrict__ opacity,
                         float* __restrict__ out)
{
    const int lane = threadIdx.x & 31;
    const int wid  = threadIdx.x >> 5;
    const int ray  = blockIdx.x * WPB + wid;
    const float POSINF = __int_as_float(0x7f800000);

    float ox = rays_o[3*ray+0], oy = rays_o[3*ray+1], oz = rays_o[3*ray+2];
    float dx = rays_d[3*ray+0], dy = rays_d[3*ray+1], dz = rays_d[3*ray+2];
    float cx = fmaf(dx, 3.0f, ox), cy = fmaf(dy, 3.0f, oy), cz = fmaf(dz, 3.0f, oz);
    float ax = -2.0f*cx, ay = -2.0f*cy, az = -2.0f*cz;
    float cn2 = cx*cx + cy*cy + cz*cz;

    // ---- seed thr: exact sample-10th-min over 1024 strided points (thr-only) ----
    float sa[KSEL];
    #pragma unroll
    for (int j = 0; j < KSEL; j++) sa[j] = POSINF;
    for (int ob = 0; ob < 8; ob++) {
        float4 q[4];                 // prefetch 4 scattered loads (MLP=4)
        #pragma unroll
        for (int ii = 0; ii < 4; ii++)
            q[ii] = __ldg(&g_pts[((ob * 4 + ii) * 32 + lane) * SEEDSTR]);
        #pragma unroll
        for (int ii = 0; ii < 4; ii++) {
            float k = fmaf(q[ii].x, ax, fmaf(q[ii].y, ay, fmaf(q[ii].z, az, q[ii].w)));
            SORT10_INS(sa, k);
        }
    }
    float thr;
    {
        float m = 0.f;
        #pragma unroll
        for (int rnd = 0; rnd < KSEL; rnd++) {
            float h = sa[0];
            #pragma unroll
            for (int off = 16; off; off >>= 1)
                h = fminf(h, __shfl_xor_sync(FULLMASK, h, off));
            m = h;
            bool c = (sa[0] == h);
            #pragma unroll
            for (int j = 0; j < KSEL-1; j++) sa[j] = c ? sa[j+1] : sa[j];
            if (c) sa[KSEL-1] = POSINF;
        }
        thr = m;                     // >= true d10^2 (sample 10th >= full 10th)
    }

    float hd[KSEL]; int hix[KSEL];
    #pragma unroll
    for (int j = 0; j < KSEL; j++) { hd[j] = POSINF; hix[j] = 0; }
    float t2 = 2.0f * sqrtf(fmaxf(thr + cn2, 0.0f));

    // ---- screened linear sweep over all 64-point chunks ----
    for (int cb = 0; cb < NCHPAD; cb += 32) {
        float4 m  = __ldg(&g_cmeta[cb + lane]);
        float rad = __ldg(&g_crad[cb + lane]);
        float kc  = fmaf(m.x, ax, fmaf(m.y, ay, fmaf(m.z, az, m.w)));
        bool pass = kc <= thr + fmaf(t2, rad, rad * rad);
        unsigned pm = __ballot_sync(FULLMASK, pass);
        while (pm) {
            int src = __ffs(pm) - 1;
            pm &= pm - 1;
            int pb = (cb + src) * CHUNK;
            float4 q0 = __ldg(&g_pts[pb + lane]);        // prefetch both groups
            float4 q1 = __ldg(&g_pts[pb + 32 + lane]);
            #pragma unroll
            for (int it = 0; it < 2; it++) {
                float4 p = it ? q1 : q0;
                int ib = pb + it * 32;
                float k = fmaf(p.x, ax, fmaf(p.y, ay, fmaf(p.z, az, p.w)));
                unsigned im = __ballot_sync(FULLMASK, k <= thr);
                while (im) {
                    int is = __ffs(im) - 1;
                    im &= im - 1;
                    float kv = __shfl_sync(FULLMASK, k, is);
                    if (kv <= thr) {
                        INSERT2(hd, hix, kv, ib + is);
                        thr = fminf(thr, hd[KSEL-1]);
                    }
                }
            }
            t2 = 2.0f * sqrtf(fmaxf(thr + cn2, 0.0f));
        }
    }

    // ---- epilogue (lane 0; all lanes hold identical heaps) ----
    if (lane == 0) {
        float ws = 0.f, e0 = 0.f, e1 = 0.f, e2 = 0.f;
        #pragma unroll
        for (int k = 0; k < KSEL; k++) {
            float dist = sqrtf(fmaxf(hd[k] + cn2, 0.0f));
            int id = __ldg(&g_sid[hix[k]]);
            float w = expf(-0.1f * dist) * sigmoidf_(opacity[id]);
            ws += w;
            e0 = fmaf(w, sigmoidf_(fdc[3*id+0]), e0);
            e1 = fmaf(w, sigmoidf_(fdc[3*id+1]), e1);
            e2 = fmaf(w, sigmoidf_(fdc[3*id+2]), e2);
        }
        float inv = 1.0f / (ws + 1e-8f);
        out[3*ray+0] = e0 * inv;
        out[3*ray+1] = e1 * inv;
        out[3*ray+2] = e2 * inv;
    }
}

extern "C" void kernel_launch(void* const* d_in, const int* in_sizes, int n_in,
                              void* d_out, int out_size)
{
    const float* rays_o  = (const float*)d_in[0];
    const float* rays_d  = (const float*)d_in[1];
    const float* xyz     = (const float*)d_in[2];
    const float* fdc     = (const float*)d_in[3];
    const float* opacity = (const float*)d_in[4];
    float* out = (float*)d_out;

    void* cnt_addr = nullptr;
    cudaGetSymbolAddress(&cnt_addr, g_cnt);
    cudaMemsetAsync(cnt_addr, 0, NCELLS * sizeof(int));

    const int PB = (NPOINTS + 1023) / 1024;
    pre_hist_kernel<<<PB, 1024>>>(xyz);
    pre_scan_kernel<<<1, 1024>>>();
    pre_scatter_kernel<<<PB, 1024>>>(xyz);
    pre_chunkmeta_kernel<<<(NCHPAD * 32) / TPB, TPB>>>();
    gsplat_sweep_kernel<<<BATCH / WPB, TPB>>>(
        rays_o, rays_d, fdc, opacity, out);
}